// round 9
// baseline (speedup 1.0000x reference)
#include <cuda_runtime.h>
#include <cuda_fp16.h>
#include <cstdint>

// Problem constants (CRF_6262062317593): B=512, S=512, T=128
#define CRF_B 512
#define CRF_S 512
#define CRF_T 128
#define BPC   16                 // batches per CTA (mma M dimension)
#define NCTA  (CRF_B / BPC)      // 32 CTAs
#define VPAD  136                // halves per V row: 272 B (16B-aligned, bank-skewed)
#define SHIFT 5.0f

// Scratch (device globals: allocations are forbidden).
__device__ float g_diff[CRF_B];
__device__ int   g_arrived = 0;

__device__ __forceinline__ uint32_t h2pack(float a, float b) {
    __half2 h = __floats2half2_rn(a, b);
    return *reinterpret_cast<uint32_t*>(&h);
}

__device__ __forceinline__ void mma16816(float& d0, float& d1, float& d2, float& d3,
                                         uint32_t a0, uint32_t a1, uint32_t a2, uint32_t a3,
                                         uint32_t b0, uint32_t b1) {
    asm volatile(
        "mma.sync.aligned.m16n8k16.row.col.f32.f16.f16.f32 "
        "{%0,%1,%2,%3}, {%4,%5,%6,%7}, {%8,%9}, {%0,%1,%2,%3};\n"
        : "+f"(d0), "+f"(d1), "+f"(d2), "+f"(d3)
        : "r"(a0), "r"(a1), "r"(a2), "r"(a3), "r"(b0), "r"(b1));
}

__device__ __forceinline__ void ldmatrix_x4(uint32_t& a0, uint32_t& a1,
                                            uint32_t& a2, uint32_t& a3, uint32_t addr) {
    asm volatile("ldmatrix.sync.aligned.m8n8.x4.shared.b16 {%0,%1,%2,%3}, [%4];"
                 : "=r"(a0), "=r"(a1), "=r"(a2), "=r"(a3) : "r"(addr));
}

__device__ __forceinline__ uint32_t smem_u32(const void* p) {
    return (uint32_t)__cvta_generic_to_shared(p);
}

// ---------------------------------------------------------------------------
// Tensor-core CRF: 32 CTAs x 16 batches, 128 threads (4 warps).
// Warp w owns tag columns [32w, 32w+32). E = exp(trans) lives in B-fragments
// (registers, loaded once). Per step: ldmatrix A from V smem -> 32 HMMA ->
// register epilogue (mask-keep, emission weight, rescale) -> STS fp16 V.
// ---------------------------------------------------------------------------
__global__ __launch_bounds__(128, 1)
void crf_mma_kernel(const float* __restrict__ em,       // (B,S,T) f32
                    const void*  __restrict__ tags,     // (B,S) i32 or i64
                    const void*  __restrict__ mask,     // (B,S) i32 or u8
                    const float* __restrict__ startT,   // (T)
                    const float* __restrict__ endT,     // (T)
                    const float* __restrict__ trans,    // (T,T)
                    float* __restrict__ out)            // scalar
{
    const int base = blockIdx.x * BPC;
    const int j    = threadIdx.x;       // 0..127
    const int w    = j >> 5;            // warp 0..3
    const int lane = j & 31;
    const int tig  = lane & 3;          // thread-in-group
    const int gid  = lane >> 2;         // group 0..7
    const int rl   = gid;               // low batch row
    const int rh   = gid + 8;           // high batch row
    const long long bl = base + rl;
    const long long bh = base + rh;

    __shared__ __align__(16) __half sV[2][BPC][VPAD];
    __shared__ float         sStart[CRF_T];
    __shared__ float         sEnd[CRF_T];
    __shared__ float         sFw[BPC][4];
    __shared__ float         sLogZ[BPC];
    __shared__ float         sFwd[BPC];
    __shared__ float         sRed[128];
    __shared__ unsigned char sMask[BPC][CRF_S];
    __shared__ short         sTags[BPC][CRF_S];
    __shared__ int           sDet[4];
    __shared__ int           sLast;

    // ---- dtype detect (validated R2: mask int32 on this harness) ----
    if (j < 64) {
        const unsigned int* tw = (const unsigned int*)tags;
        const unsigned int* mw = (const unsigned int*)mask;
        const int zero = (tw[2 * j + 1] == 0u) ? 1 : 0;
        const int big  = (mw[j] > 1u) ? 1 : 0;
        const unsigned zm = __ballot_sync(0xffffffffu, zero);
        const unsigned bm = __ballot_sync(0xffffffffu, big);
        if (lane == 0) { sDet[w] = __popc(zm); sDet[2 + w] = __popc(bm); }
    }
    __syncthreads();
    const int tags_is64 = ((sDet[0] + sDet[1]) >= 48);
    const int mask_is32 = ((sDet[2] + sDet[3]) == 0);

    // ---- stage start/end/mask/tags ----
    if (j < CRF_T) { sStart[j] = startT[j]; sEnd[j] = endT[j]; }
    if (mask_is32) {
        const int* m = (const int*)mask;
        for (int idx = j; idx < BPC * CRF_S; idx += 128) {
            const int bb = idx >> 9, s = idx & (CRF_S - 1);
            sMask[bb][s] = (m[(size_t)(base + bb) * CRF_S + s] != 0);
        }
    } else {
        const unsigned char* m = (const unsigned char*)mask;
        for (int idx = j; idx < BPC * CRF_S; idx += 128) {
            const int bb = idx >> 9, s = idx & (CRF_S - 1);
            sMask[bb][s] = (m[(size_t)(base + bb) * CRF_S + s] != 0);
        }
    }
    if (tags_is64) {
        const long long* t = (const long long*)tags;
        for (int idx = j; idx < BPC * CRF_S; idx += 128) {
            const int bb = idx >> 9, s = idx & (CRF_S - 1);
            sTags[bb][s] = (short)t[(size_t)(base + bb) * CRF_S + s];
        }
    } else {
        const int* t = (const int*)tags;
        for (int idx = j; idx < BPC * CRF_S; idx += 128) {
            const int bb = idx >> 9, s = idx & (CRF_S - 1);
            sTags[bb][s] = (short)t[(size_t)(base + bb) * CRF_S + s];
        }
    }

    // ---- E = exp(trans) as persistent B fragments (m16n8k16, col layout) ----
    // Bf[c][t][0] = {E[k0][n], E[k0+1][n]}, Bf[c][t][1] = {E[k0+8][n], E[k0+9][n]}
    // with k0 = 16c + 2*tig, n = 32w + 8t + gid.
    uint32_t Bf[8][4][2];
#pragma unroll
    for (int c = 0; c < 8; c++) {
#pragma unroll
        for (int t = 0; t < 4; t++) {
            const int n  = w * 32 + t * 8 + gid;
            const int k0 = c * 16 + tig * 2;
            Bf[c][t][0] = h2pack(__expf(trans[(k0)     * CRF_T + n]),
                                 __expf(trans[(k0 + 1) * CRF_T + n]));
            Bf[c][t][1] = h2pack(__expf(trans[(k0 + 8) * CRF_T + n]),
                                 __expf(trans[(k0 + 9) * CRF_T + n]));
        }
    }
    __syncthreads();   // sStart ready

    // ---- t=0 init: v = exp(start + em0 - m00[row]) ----
    // vprev index: t*4 + {0,1}=low-row cols {2tig, 2tig+1}, t*4 + {2,3}=high-row
    float vprev[16], wreg[16];
    const float m00l = sStart[0] + em[(size_t)bl * CRF_S * CRF_T];
    const float m00h = sStart[0] + em[(size_t)bh * CRF_S * CRF_T];
    float logZl = m00l, logZh = m00h;
    int nstepl = 0, nsteph = 0;
#pragma unroll
    for (int t = 0; t < 4; t++) {
        const int colb = w * 32 + t * 8 + 2 * tig;
        const float2 e0l = *(const float2*)&em[((size_t)bl * CRF_S) * CRF_T + colb];
        const float2 e0h = *(const float2*)&em[((size_t)bh * CRF_S) * CRF_T + colb];
        vprev[t*4+0] = __expf(sStart[colb]     + e0l.x - m00l);
        vprev[t*4+1] = __expf(sStart[colb + 1] + e0l.y - m00l);
        vprev[t*4+2] = __expf(sStart[colb]     + e0h.x - m00h);
        vprev[t*4+3] = __expf(sStart[colb + 1] + e0h.y - m00h);
        *(uint32_t*)&sV[0][rl][colb] = h2pack(vprev[t*4+0], vprev[t*4+1]);
        *(uint32_t*)&sV[0][rh][colb] = h2pack(vprev[t*4+2], vprev[t*4+3]);
        // prefetch step-1 emission weights
        const float2 e1l = *(const float2*)&em[((size_t)bl * CRF_S + 1) * CRF_T + colb];
        const float2 e1h = *(const float2*)&em[((size_t)bh * CRF_S + 1) * CRF_T + colb];
        wreg[t*4+0] = __expf(e1l.x - SHIFT);
        wreg[t*4+1] = __expf(e1l.y - SHIFT);
        wreg[t*4+2] = __expf(e1h.x - SHIFT);
        wreg[t*4+3] = __expf(e1h.y - SHIFT);
    }

    // ldmatrix lane address template
    const int tile = lane >> 3;
    const int rrow = (lane & 7) + ((tile & 1) << 3);
    const uint32_t lmoff = (uint32_t)(rrow * (VPAD * 2) + ((tile >> 1) << 4));
    const uint32_t svu[2] = { smem_u32(&sV[0][0][0]), smem_u32(&sV[1][0][0]) };
    __syncthreads();   // sV[0] visible

    for (int s = 1; s < CRF_S; s++) {
        const int p = (s + 1) & 1;   // read buffer
        const int q = s & 1;         // write buffer

        // prefetch next emissions (off-chain; clamped)
        const int sn = (s + 1 < CRF_S) ? (s + 1) : (CRF_S - 1);
        float2 enl[4], enh[4];
#pragma unroll
        for (int t = 0; t < 4; t++) {
            const int colb = w * 32 + t * 8 + 2 * tig;
            enl[t] = *(const float2*)&em[((size_t)bl * CRF_S + sn) * CRF_T + colb];
            enh[t] = *(const float2*)&em[((size_t)bh * CRF_S + sn) * CRF_T + colb];
        }
        const int mkl = sMask[rl][s];
        const int mkh = sMask[rh][s];

        // D = V @ E  (8 k-chunks, 4 n-tiles)
        float D[4][4];
#pragma unroll
        for (int t = 0; t < 4; t++) { D[t][0] = D[t][1] = D[t][2] = D[t][3] = 0.f; }
#pragma unroll
        for (int c = 0; c < 8; c++) {
            uint32_t a0, a1, a2, a3;
            ldmatrix_x4(a0, a1, a2, a3, svu[p] + lmoff + c * 32);
#pragma unroll
            for (int t = 0; t < 4; t++)
                mma16816(D[t][0], D[t][1], D[t][2], D[t][3],
                         a0, a1, a2, a3, Bf[c][t][0], Bf[c][t][1]);
        }

        // epilogue in registers
        float invl = 1.f, invh = 1.f;
        const bool resc = ((s & 3) == 0);
        if (resc) {
            const float ccl = __half2float(sV[p][rl][0]);
            const float cch = __half2float(sV[p][rh][0]);
            invl = __fdividef(1.f, ccl);
            invh = __fdividef(1.f, cch);
            logZl += __logf(ccl);
            logZh += __logf(cch);
        }
        nstepl += mkl;
        nsteph += mkh;
#pragma unroll
        for (int t = 0; t < 4; t++) {
            const int colb = w * 32 + t * 8 + 2 * tig;
            float v0 = mkl ? D[t][0] * wreg[t*4+0] : vprev[t*4+0];
            float v1 = mkl ? D[t][1] * wreg[t*4+1] : vprev[t*4+1];
            float v2 = mkh ? D[t][2] * wreg[t*4+2] : vprev[t*4+2];
            float v3 = mkh ? D[t][3] * wreg[t*4+3] : vprev[t*4+3];
            v0 *= invl; v1 *= invl; v2 *= invh; v3 *= invh;
            vprev[t*4+0] = v0; vprev[t*4+1] = v1;
            vprev[t*4+2] = v2; vprev[t*4+3] = v3;
            *(uint32_t*)&sV[q][rl][colb] = h2pack(v0, v1);
            *(uint32_t*)&sV[q][rh][colb] = h2pack(v2, v3);
            wreg[t*4+0] = __expf(enl[t].x - SHIFT);
            wreg[t*4+1] = __expf(enl[t].y - SHIFT);
            wreg[t*4+2] = __expf(enh[t].x - SHIFT);
            wreg[t*4+3] = __expf(enh[t].y - SHIFT);
        }
        __syncthreads();
    }
    logZl += SHIFT * (float)nstepl;
    logZh += SHIFT * (float)nsteph;

    // ---- final: fwd[row] = log(sum_col v * exp(end)) + logZ[row] ----
    {
        float pl = 0.f, ph = 0.f;
#pragma unroll
        for (int t = 0; t < 4; t++) {
            const int colb = w * 32 + t * 8 + 2 * tig;
            pl += vprev[t*4+0] * __expf(sEnd[colb])
                + vprev[t*4+1] * __expf(sEnd[colb + 1]);
            ph += vprev[t*4+2] * __expf(sEnd[colb])
                + vprev[t*4+3] * __expf(sEnd[colb + 1]);
        }
        pl += __shfl_xor_sync(0xffffffffu, pl, 1);
        pl += __shfl_xor_sync(0xffffffffu, pl, 2);
        ph += __shfl_xor_sync(0xffffffffu, ph, 1);
        ph += __shfl_xor_sync(0xffffffffu, ph, 2);
        if (tig == 0) { sFw[rl][w] = pl; sFw[rh][w] = ph; }
        if (w == 0 && tig == 0) { sLogZ[rl] = logZl; sLogZ[rh] = logZh; }
    }
    __syncthreads();
    if (j < BPC)
        sFwd[j] = __logf((sFw[j][0] + sFw[j][1]) + (sFw[j][2] + sFw[j][3])) + sLogZ[j];
    __syncthreads();

    // ---- gold scores: warp w handles batches 4w..4w+3 (warp-local reduce) ----
    for (int qq = 0; qq < 4; qq++) {
        const int bb = w * 4 + qq;
        const long long bg = base + bb;
        float part = 0.f;
        int cnt = 0;
        for (int s = lane; s < CRF_S; s += 32) {
            const int mk = sMask[bb][s] ? 1 : 0;
            cnt += mk;
            if (s >= 1 && mk) {
                const int tp = (int)sTags[bb][s - 1];
                const int tc = (int)sTags[bb][s];
                part += trans[tp * CRF_T + tc]
                      + em[((size_t)bg * CRF_S + s) * CRF_T + tc];
            }
        }
#pragma unroll
        for (int off = 16; off; off >>= 1) {
            part += __shfl_xor_sync(0xffffffffu, part, off);
            cnt  += __shfl_xor_sync(0xffffffffu, cnt, off);
        }
        if (lane == 0) {
            const int tg0 = (int)sTags[bb][0];
            float gold = part + sStart[tg0]
                       + em[((size_t)bg * CRF_S) * CRF_T + tg0];
            const int seq_end = cnt - 1;
            gold += sEnd[(int)sTags[bb][seq_end]];
            g_diff[bg] = sFwd[bb] - gold;
        }
    }

    // ---- grid-finish: last CTA computes the deterministic mean ----
    __syncthreads();
    if (j == 0) {
        __threadfence();
        const int ticket = atomicAdd(&g_arrived, 1);
        sLast = (ticket == NCTA - 1);
    }
    __syncthreads();
    if (sLast) {
        __threadfence();
        float acc = g_diff[j] + g_diff[j + 128] + g_diff[j + 256] + g_diff[j + 384];
        sRed[j] = acc;
        __syncthreads();
#pragma unroll
        for (int stride = 64; stride > 0; stride >>= 1) {
            if (j < stride) sRed[j] += sRed[j + stride];
            __syncthreads();
        }
        if (j == 0) {
            out[0] = sRed[0] * (1.0f / (float)CRF_B);
            g_arrived = 0;
        }
    }
}

extern "C" void kernel_launch(void* const* d_in, const int* in_sizes, int n_in,
                              void* d_out, int out_size)
{
    const float* emissions = (const float*)d_in[0];
    const void*  tags      = d_in[1];
    const void*  mask      = d_in[2];
    const float* startT    = (const float*)d_in[3];
    const float* endT      = (const float*)d_in[4];
    const float* trans     = (const float*)d_in[5];
    float*       out       = (float*)d_out;

    crf_mma_kernel<<<NCTA, 128>>>(emissions, tags, mask,
                                  startT, endT, trans, out);
}

// round 10
// speedup vs baseline: 1.5750x; 1.5750x over previous
#include <cuda_runtime.h>
#include <cuda_fp16.h>
#include <cstdint>

// Problem constants (CRF_6262062317593): B=512, S=512, T=128
#define CRF_B 512
#define CRF_S 512
#define CRF_T 128
#define SHIFT 5.0f   // ~log(T): per-step normalizer folded into exp(emission)

// Scratch (device globals: allocations are forbidden).
__device__ float g_diff[CRF_B];
__device__ int   g_arrived = 0;   // grid-finish ticket (reset by last CTA)

__device__ __forceinline__ __half2 u32_as_h2(unsigned int u) {
    return *reinterpret_cast<__half2*>(&u);
}

// ---------------------------------------------------------------------------
// Fused kernel: one batch per CTA, 256 threads (8 warps). Warp w owns tag
// columns [16w, 16w+16). Lanes l and l^16 split the 128-term dot of column
// 16w+(l&15): each reduces 64 i-terms (32 HFMA2, 32 half2 E-regs), partials
// combined with ONE shfl_xor(16) — no extra barrier, no smem round-trip, no
// idle threads (R8's mistakes). One __syncthreads per step, as in R7.
// ---------------------------------------------------------------------------
__global__ __launch_bounds__(256, 4)
void crf_fused_kernel(const float* __restrict__ em,       // (B,S,T) f32
                      const void*  __restrict__ tags,     // (B,S) i32 or i64
                      const void*  __restrict__ mask,     // (B,S) i32 or u8
                      const float* __restrict__ startT,   // (T)
                      const float* __restrict__ endT,     // (T)
                      const float* __restrict__ trans,    // (T,T)
                      float* __restrict__ out)            // scalar
{
    const int b    = blockIdx.x;
    const int j    = threadIdx.x;       // 0..255
    const int lane = j & 31;
    const int warp = j >> 5;            // 0..7
    const int col  = warp * 16 + (lane & 15);   // tag column (each twice/warp)
    const int half = (lane >> 4) & 1;           // i-range half

    const float* __restrict__ emb = em + (size_t)b * CRF_S * CRF_T;

    __shared__ __align__(16) __half sV[2][CRF_T];
    __shared__ float         sRed[8];
    __shared__ float         sPart[256];
    __shared__ int           sCnt[256];
    __shared__ unsigned char sMask[CRF_S];
    __shared__ short         sTags[CRF_S];
    __shared__ int           sDet[4];
    __shared__ int           sLast;
    __shared__ float         sFwd;

    // ---- inline dtype detect (validated R2: mask int32 on this harness) ----
    if (j < 64) {
        const unsigned int* tw = (const unsigned int*)tags;
        const unsigned int* mw = (const unsigned int*)mask;
        const int zero = (tw[2 * j + 1] == 0u) ? 1 : 0;
        const int big  = (mw[j] > 1u) ? 1 : 0;
        const unsigned zm = __ballot_sync(0xffffffffu, zero);
        const unsigned bm = __ballot_sync(0xffffffffu, big);
        if (lane == 0) { sDet[warp] = __popc(zm); sDet[2 + warp] = __popc(bm); }
    }
    __syncthreads();
    const int tags_is64 = ((sDet[0] + sDet[1]) >= 48);
    const int mask_is32 = ((sDet[2] + sDet[3]) == 0);

    // ---- stage mask + tags with detected widths ----
    if (mask_is32) {
        const int* m0 = (const int*)mask + (size_t)b * CRF_S;
        for (int s = j; s < CRF_S; s += 256) sMask[s] = (m0[s] != 0);
    } else {
        const unsigned char* m0 = (const unsigned char*)mask + (size_t)b * CRF_S;
        for (int s = j; s < CRF_S; s += 256) sMask[s] = (m0[s] != 0);
    }
    if (tags_is64) {
        const long long* t0 = (const long long*)tags + (size_t)b * CRF_S;
        for (int s = j; s < CRF_S; s += 256) sTags[s] = (short)t0[s];
    } else {
        const int* t0 = (const int*)tags + (size_t)b * CRF_S;
        for (int s = j; s < CRF_S; s += 256) sTags[s] = (short)t0[s];
    }

    // ---- E half-column: Eh[k] = (E[i0+2k][col], E[i0+2k+1][col]), i0=64*half
    __half2 Eh[32];
    {
        const int i0 = 64 * half;
#pragma unroll
        for (int k = 0; k < 32; k++) {
            const float e0 = __expf(trans[(i0 + 2 * k) * CRF_T + col]);
            const float e1 = __expf(trans[(i0 + 2 * k + 1) * CRF_T + col]);
            Eh[k] = __floats2half2_rn(e0, e1);
        }
    }

    // ---- t = 0 init: v = exp(start + em0 - m00); both halves track state ----
    const float m00 = startT[0] + emb[0];
    float v = __expf(startT[col] + emb[col] - m00);
    float logZ = m00;
    int   nstep = 0;
    if (half == 0) sV[0][col] = __float2half_rn(v);

    float w = __expf(emb[CRF_T + col] - SHIFT);
    __syncthreads();

    for (int s = 1; s < CRF_S; s++) {
        const int p = (s + 1) & 1;
        const int q = s & 1;

        // branchless prefetch of next emission (clamped; unused at s=S-1)
        const int sn = (s + 1 < CRF_S) ? (s + 1) : (CRF_S - 1);
        const float en = emb[(size_t)sn * CRF_T + col];
        const int mk = sMask[s];

        // 8 LDS.128: the 64 halves of v for this thread's i-half
        const uint4* r = (const uint4*)&sV[p][64 * half];
        __half2 A0 = __half2half2(__ushort_as_half(0));
        __half2 A1 = A0, A2 = A0, A3 = A0;
#pragma unroll
        for (int i = 0; i < 8; i++) {
            const uint4 x = r[i];
            A0 = __hfma2(u32_as_h2(x.x), Eh[4 * i + 0], A0);
            A1 = __hfma2(u32_as_h2(x.y), Eh[4 * i + 1], A1);
            A2 = __hfma2(u32_as_h2(x.z), Eh[4 * i + 2], A2);
            A3 = __hfma2(u32_as_h2(x.w), Eh[4 * i + 3], A3);
        }
        // short combine: 2 HADD2 levels, then fp32
        const __half2 Aa = __hadd2(A0, A1);
        const __half2 Ab = __hadd2(A2, A3);
        const __half2 Ac = __hadd2(Aa, Ab);
        const float2  f  = __half22float2(Ac);
        const float  part = f.x + f.y;
        const float  dot  = part + __shfl_xor_sync(0xffffffffu, part, 16);

        float vn = mk ? dot * w : v;     // both halves compute identically
        nstep += mk;

        if ((s & 3) == 0) {              // rescale every 4 steps (fp16 range)
            const float cc = __half2float(sV[p][0]);
            vn *= __fdividef(1.0f, cc);
            logZ += __logf(cc);
        }

        if (half == 0) sV[q][col] = __float2half_rn(vn);
        v = vn;

        w = __expf(en - SHIFT);
        __syncthreads();
    }
    logZ += SHIFT * (float)nstep;

    // ---- final: fwd = log(sum_col v * exp(end)) + logZ ----
    // Only half==0 lanes (0..15 of each warp) carry distinct columns.
    {
        float t0 = v * __expf(endT[col]);
#pragma unroll
        for (int off = 8; off; off >>= 1)
            t0 += __shfl_xor_sync(0xffffffffu, t0, off);   // reduce lanes 0..15
        if (lane == 0) sRed[warp] = t0;
    }
    __syncthreads();
    if (j == 0) {
        const float tot = ((sRed[0] + sRed[1]) + (sRed[2] + sRed[3]))
                        + ((sRed[4] + sRed[5]) + (sRed[6] + sRed[7]));
        sFwd = __logf(tot) + logZ;
    }

    // ---- gold score (fp32, fixed-order tree reduce over 256 threads) ----
    {
        float part = 0.f;
        int cnt = 0;
        for (int s = j; s < CRF_S; s += 256) {
            const int mk = sMask[s] ? 1 : 0;
            cnt += mk;
            if (s >= 1 && mk) {
                const int tp = (int)sTags[s - 1];
                const int tc = (int)sTags[s];
                part += trans[tp * CRF_T + tc] + emb[(size_t)s * CRF_T + tc];
            }
        }
        __syncthreads();
        sPart[j] = part;
        sCnt[j] = cnt;
        __syncthreads();
#pragma unroll
        for (int stride = 128; stride > 0; stride >>= 1) {
            if (j < stride) {
                sPart[j] += sPart[j + stride];
                sCnt[j]  += sCnt[j + stride];
            }
            __syncthreads();
        }
        if (j == 0) {
            const int tg0 = (int)sTags[0];
            float gold = sPart[0] + startT[tg0] + emb[tg0];
            const int seq_end = sCnt[0] - 1;
            gold += endT[(int)sTags[seq_end]];
            g_diff[b] = sFwd - gold;
        }
    }

    // ---- grid-finish: last CTA does the deterministic mean ----
    __syncthreads();
    if (j == 0) {
        __threadfence();
        const int ticket = atomicAdd(&g_arrived, 1);
        sLast = (ticket == CRF_B - 1);
    }
    __syncthreads();
    if (sLast) {
        __threadfence();
        float acc = g_diff[j] + g_diff[j + 256];
        sPart[j] = acc;
        __syncthreads();
#pragma unroll
        for (int stride = 128; stride > 0; stride >>= 1) {
            if (j < stride) sPart[j] += sPart[j + stride];
            __syncthreads();
        }
        if (j == 0) {
            out[0] = sPart[0] * (1.0f / (float)CRF_B);
            g_arrived = 0;
        }
    }
}

extern "C" void kernel_launch(void* const* d_in, const int* in_sizes, int n_in,
                              void* d_out, int out_size)
{
    const float* emissions = (const float*)d_in[0];
    const void*  tags      = d_in[1];
    const void*  mask      = d_in[2];
    const float* startT    = (const float*)d_in[3];
    const float* endT      = (const float*)d_in[4];
    const float* trans     = (const float*)d_in[5];
    float*       out       = (float*)d_out;

    crf_fused_kernel<<<CRF_B, 256>>>(emissions, tags, mask,
                                     startT, endT, trans, out);
}

// round 11
// speedup vs baseline: 1.7910x; 1.1371x over previous
#include <cuda_runtime.h>
#include <cuda_fp16.h>
#include <cstdint>

// Problem constants (CRF_6262062317593): B=512, S=512, T=128
#define CRF_B 512
#define CRF_S 512
#define CRF_T 128
#define SHIFT 5.0f               // per-step normalizer in w = exp(em - SHIFT)
#define LN4   1.3862944f         // E is scaled by 1/4; tracked via logZ

// Scratch (device globals: allocations are forbidden).
__device__ float g_diff[CRF_B];
__device__ int   g_arrived = 0;

__device__ __forceinline__ __half2 u32_as_h2(unsigned int u) {
    return *reinterpret_cast<__half2*>(&u);
}

// ---------------------------------------------------------------------------
// Fused kernel: one batch per CTA, 128 threads. Thread j owns tag column j:
// full 128-term dot as 64 HFMA2 into 4 fp16 accumulators (E column scaled by
// 1/4 so 32-term fp16 accs can't overflow; the rescale-every-4-steps self-
// corrects the constant via logZ). Combine = 3 HADD2 + 1 F2F + 1 FADD.
// Loop unrolled x2 so double-buffer selection is compile-time.
// ---------------------------------------------------------------------------
__global__ __launch_bounds__(CRF_T, 4)
void crf_fused_kernel(const float* __restrict__ em,       // (B,S,T) f32
                      const void*  __restrict__ tags,     // (B,S) i32 or i64
                      const void*  __restrict__ mask,     // (B,S) i32 or u8
                      const float* __restrict__ startT,   // (T)
                      const float* __restrict__ endT,     // (T)
                      const float* __restrict__ trans,    // (T,T)
                      float* __restrict__ out)            // scalar
{
    const int b    = blockIdx.x;
    const int j    = threadIdx.x;       // 0..127
    const int lane = j & 31;
    const int warp = j >> 5;

    const float* __restrict__ emb = em + (size_t)b * CRF_S * CRF_T;

    __shared__ __align__(16) __half sV[2][CRF_T];
    __shared__ float         sRed[4];
    __shared__ float         sPart[CRF_T];
    __shared__ int           sCnt[CRF_T];
    __shared__ unsigned char sMask[CRF_S];
    __shared__ short         sTags[CRF_S];
    __shared__ int           sDet[4];
    __shared__ int           sLast;

    // ---- inline dtype detect (validated R2: mask int32 on this harness) ----
    if (j < 64) {
        const unsigned int* tw = (const unsigned int*)tags;
        const unsigned int* mw = (const unsigned int*)mask;
        const int zero = (tw[2 * j + 1] == 0u) ? 1 : 0;
        const int big  = (mw[j] > 1u) ? 1 : 0;
        const unsigned zm = __ballot_sync(0xffffffffu, zero);
        const unsigned bm = __ballot_sync(0xffffffffu, big);
        if (lane == 0) { sDet[warp] = __popc(zm); sDet[2 + warp] = __popc(bm); }
    }
    __syncthreads();
    const int tags_is64 = ((sDet[0] + sDet[1]) >= 48);
    const int mask_is32 = ((sDet[2] + sDet[3]) == 0);

    // ---- stage mask + tags with detected widths ----
    if (mask_is32) {
        const int* m0 = (const int*)mask + (size_t)b * CRF_S;
        for (int s = j; s < CRF_S; s += CRF_T) sMask[s] = (m0[s] != 0);
    } else {
        const unsigned char* m0 = (const unsigned char*)mask + (size_t)b * CRF_S;
        for (int s = j; s < CRF_S; s += CRF_T) sMask[s] = (m0[s] != 0);
    }
    if (tags_is64) {
        const long long* t0 = (const long long*)tags + (size_t)b * CRF_S;
        for (int s = j; s < CRF_S; s += CRF_T) sTags[s] = (short)t0[s];
    } else {
        const int* t0 = (const int*)tags + (size_t)b * CRF_S;
        for (int s = j; s < CRF_S; s += CRF_T) sTags[s] = (short)t0[s];
    }

    // ---- E column j, scaled by 1/4: Eh[k] = (E[2k][j], E[2k+1][j]) / 4 ----
    __half2 Eh[CRF_T / 2];
#pragma unroll
    for (int k = 0; k < CRF_T / 2; k++) {
        const float e0 = 0.25f * __expf(trans[(2 * k) * CRF_T + j]);
        const float e1 = 0.25f * __expf(trans[(2 * k + 1) * CRF_T + j]);
        Eh[k] = __floats2half2_rn(e0, e1);
    }

    // ---- t = 0 init ----
    const float m00 = startT[0] + emb[0];
    float v = __expf(startT[j] + emb[j] - m00);
    float logZ = m00;
    int   nstep = 0;
    sV[0][j] = __float2half_rn(v);
    float w = __expf(emb[CRF_T + j] - SHIFT);
    __syncthreads();

    // ---- one forward step: read buffer P, write buffer Q (compile-time) ----
#define CRF_STEP(SV, P, Q)                                                     \
    {                                                                          \
        const int sn = ((SV) + 1 < CRF_S) ? (SV) + 1 : (CRF_S - 1);            \
        const float en = emb[(size_t)sn * CRF_T + j];                          \
        const int mk = sMask[(SV)];                                            \
        const uint4* r = (const uint4*)sV[(P)];                                \
        const uint4 x0 = r[0];                                                 \
        __half2 A0 = __half2half2(__ushort_as_half(0));                        \
        __half2 A1 = A0, A2 = A0, A3 = A0;                                     \
        A0 = __hfma2(u32_as_h2(x0.x), Eh[0], A0);                              \
        A1 = __hfma2(u32_as_h2(x0.y), Eh[1], A1);                              \
        A2 = __hfma2(u32_as_h2(x0.z), Eh[2], A2);                              \
        A3 = __hfma2(u32_as_h2(x0.w), Eh[3], A3);                              \
        _Pragma("unroll")                                                      \
        for (int i = 1; i < 16; i++) {                                         \
            const uint4 x = r[i];                                              \
            A0 = __hfma2(u32_as_h2(x.x), Eh[4 * i + 0], A0);                   \
            A1 = __hfma2(u32_as_h2(x.y), Eh[4 * i + 1], A1);                   \
            A2 = __hfma2(u32_as_h2(x.z), Eh[4 * i + 2], A2);                   \
            A3 = __hfma2(u32_as_h2(x.w), Eh[4 * i + 3], A3);                   \
        }                                                                      \
        const __half2 Ac = __hadd2(__hadd2(A0, A1), __hadd2(A2, A3));          \
        const float2 f = __half22float2(Ac);                                   \
        const float dot = f.x + f.y;                                           \
        float vn = mk ? dot * w : v;                                           \
        nstep += mk;                                                           \
        if (((SV) & 3) == 0) { /* rescale: anchor = sum of first 8 v's */      \
            const __half2 c2 = __hadd2(__hadd2(u32_as_h2(x0.x),                \
                                               u32_as_h2(x0.y)),               \
                                       __hadd2(u32_as_h2(x0.z),                \
                                               u32_as_h2(x0.w)));              \
            const float2 cf = __half22float2(c2);                              \
            const float cc = cf.x + cf.y;                                      \
            vn *= __fdividef(1.0f, cc);                                        \
            logZ += __logf(cc);                                                \
        }                                                                      \
        sV[(Q)][j] = __float2half_rn(vn);                                      \
        v = vn;                                                                \
        w = __expf(en - SHIFT);                                                \
        __syncthreads();                                                       \
    }

    CRF_STEP(1, 0, 1);
    for (int s = 2; s < CRF_S; s += 2) {
        CRF_STEP(s, 1, 0);
        CRF_STEP(s + 1, 0, 1);
    }
#undef CRF_STEP

    logZ += (SHIFT + LN4) * (float)nstep;

    // ---- final: fwd = log(sum_j v_j * exp(end_j)) + logZ ----
    const float ej = __expf(endT[j]);
    float t0 = v * ej;
#pragma unroll
    for (int off = 16; off; off >>= 1)
        t0 += __shfl_xor_sync(0xffffffffu, t0, off);
    if (lane == 0) sRed[warp] = t0;
    __syncthreads();
    const float fwd = __logf((sRed[0] + sRed[1]) + (sRed[2] + sRed[3])) + logZ;

    // ---- gold score (fp32, fixed-order tree reduce) ----
    {
        float part = 0.f;
        int cnt = 0;
        for (int s = j; s < CRF_S; s += CRF_T) {
            const int mk = sMask[s] ? 1 : 0;
            cnt += mk;
            if (s >= 1 && mk) {
                const int tp = (int)sTags[s - 1];
                const int tc = (int)sTags[s];
                part += trans[tp * CRF_T + tc] + emb[(size_t)s * CRF_T + tc];
            }
        }
        sPart[j] = part;
        sCnt[j]  = cnt;
        __syncthreads();
#pragma unroll
        for (int stride = CRF_T / 2; stride > 0; stride >>= 1) {
            if (j < stride) {
                sPart[j] += sPart[j + stride];
                sCnt[j]  += sCnt[j + stride];
            }
            __syncthreads();
        }
        if (j == 0) {
            const int tg0 = (int)sTags[0];
            float gold = sPart[0] + startT[tg0] + emb[tg0];
            const int seq_end = sCnt[0] - 1;
            gold += endT[(int)sTags[seq_end]];
            g_diff[b] = fwd - gold;
        }
    }

    // ---- grid-finish: last CTA does the deterministic mean ----
    __syncthreads();
    if (j == 0) {
        __threadfence();
        const int ticket = atomicAdd(&g_arrived, 1);
        sLast = (ticket == CRF_B - 1);
    }
    __syncthreads();
    if (sLast) {
        __threadfence();
        float acc = g_diff[j] + g_diff[j + 128] + g_diff[j + 256] + g_diff[j + 384];
        sPart[j] = acc;
        __syncthreads();
#pragma unroll
        for (int stride = CRF_T / 2; stride > 0; stride >>= 1) {
            if (j < stride) sPart[j] += sPart[j + stride];
            __syncthreads();
        }
        if (j == 0) {
            out[0] = sPart[0] * (1.0f / (float)CRF_B);
            g_arrived = 0;
        }
    }
}

extern "C" void kernel_launch(void* const* d_in, const int* in_sizes, int n_in,
                              void* d_out, int out_size)
{
    const float* emissions = (const float*)d_in[0];
    const void*  tags      = d_in[1];
    const void*  mask      = d_in[2];
    const float* startT    = (const float*)d_in[3];
    const float* endT      = (const float*)d_in[4];
    const float* trans     = (const float*)d_in[5];
    float*       out       = (float*)d_out;

    crf_fused_kernel<<<CRF_B, CRF_T>>>(emissions, tags, mask,
                                       startT, endT, trans, out);
}

// round 13
// speedup vs baseline: 1.8274x; 1.0203x over previous
#include <cuda_runtime.h>
#include <cuda_fp16.h>
#include <cstdint>

// Problem constants (CRF_6262062317593): B=512, S=512, T=128
#define CRF_B 512
#define CRF_S 512
#define CRF_T 128
#define SHIFT 5.0f               // per-step normalizer in w = exp(em - SHIFT)
#define LN4   1.3862944f         // E is scaled by 1/4; tracked via logZ

// Scratch (device globals: allocations are forbidden).
__device__ float g_diff[CRF_B];
__device__ int   g_arrived = 0;

__device__ __forceinline__ __half2 u32_as_h2(unsigned int u) {
    return *reinterpret_cast<__half2*>(&u);
}

// ---------------------------------------------------------------------------
// Fused kernel: one batch per CTA, 128 threads. Thread (warp, lane) owns
// i-half h = lane>>4 and TWO tag columns c0 = 16*warp + (lane&15), c1 = c0+64.
// Each 16B v-load feeds both column dots (LDS per CTA halved vs R11).
// Half-dot per column = 64 terms = 32 half2 E entries (EhA[32]/EhB[32] —
// R12's bug was declaring these [16]). Halves combined with one shfl_xor(16).
// ---------------------------------------------------------------------------
__global__ __launch_bounds__(CRF_T, 4)
void crf_fused_kernel(const float* __restrict__ em,       // (B,S,T) f32
                      const void*  __restrict__ tags,     // (B,S) i32 or i64
                      const void*  __restrict__ mask,     // (B,S) i32 or u8
                      const float* __restrict__ startT,   // (T)
                      const float* __restrict__ endT,     // (T)
                      const float* __restrict__ trans,    // (T,T)
                      float* __restrict__ out)            // scalar
{
    const int b    = blockIdx.x;
    const int j    = threadIdx.x;       // 0..127
    const int lane = j & 31;
    const int warp = j >> 5;            // 0..3
    const int h    = lane >> 4;         // i-half (0: i<64, 1: i>=64)
    const int c0   = warp * 16 + (lane & 15);
    const int c1   = c0 + 64;

    const float* __restrict__ emb = em + (size_t)b * CRF_S * CRF_T;

    __shared__ __align__(16) __half sV[2][CRF_T];
    __shared__ float         sRed[4];
    __shared__ float         sPart[CRF_T];
    __shared__ int           sCnt[CRF_T];
    __shared__ unsigned char sMask[CRF_S];
    __shared__ short         sTags[CRF_S];
    __shared__ int           sDet[4];
    __shared__ int           sLast;

    // ---- inline dtype detect (validated R2: mask int32 on this harness) ----
    if (j < 64) {
        const unsigned int* tw = (const unsigned int*)tags;
        const unsigned int* mw = (const unsigned int*)mask;
        const int zero = (tw[2 * j + 1] == 0u) ? 1 : 0;
        const int big  = (mw[j] > 1u) ? 1 : 0;
        const unsigned zm = __ballot_sync(0xffffffffu, zero);
        const unsigned bm = __ballot_sync(0xffffffffu, big);
        if (lane == 0) { sDet[warp] = __popc(zm); sDet[2 + warp] = __popc(bm); }
    }
    __syncthreads();
    const int tags_is64 = ((sDet[0] + sDet[1]) >= 48);
    const int mask_is32 = ((sDet[2] + sDet[3]) == 0);

    // ---- stage mask + tags with detected widths ----
    if (mask_is32) {
        const int* m0 = (const int*)mask + (size_t)b * CRF_S;
        for (int s = j; s < CRF_S; s += CRF_T) sMask[s] = (m0[s] != 0);
    } else {
        const unsigned char* m0 = (const unsigned char*)mask + (size_t)b * CRF_S;
        for (int s = j; s < CRF_S; s += CRF_T) sMask[s] = (m0[s] != 0);
    }
    if (tags_is64) {
        const long long* t0 = (const long long*)tags + (size_t)b * CRF_S;
        for (int s = j; s < CRF_S; s += CRF_T) sTags[s] = (short)t0[s];
    } else {
        const int* t0 = (const int*)tags + (size_t)b * CRF_S;
        for (int s = j; s < CRF_S; s += CRF_T) sTags[s] = (short)t0[s];
    }

    // ---- E half-columns (scaled by 1/4) for cols c0 and c1 over i-half h ----
    // EhA[k] = (E[i0+2k][c0], E[i0+2k+1][c0])/4, k = 0..31; i0 = 64h.
    __half2 EhA[32], EhB[32];
    {
        const int i0 = 64 * h;
#pragma unroll
        for (int k = 0; k < 32; k++) {
            const float a0 = 0.25f * __expf(trans[(i0 + 2 * k)     * CRF_T + c0]);
            const float a1 = 0.25f * __expf(trans[(i0 + 2 * k + 1) * CRF_T + c0]);
            EhA[k] = __floats2half2_rn(a0, a1);
            const float b0 = 0.25f * __expf(trans[(i0 + 2 * k)     * CRF_T + c1]);
            const float b1 = 0.25f * __expf(trans[(i0 + 2 * k + 1) * CRF_T + c1]);
            EhB[k] = __floats2half2_rn(b0, b1);
        }
    }

    // ---- t = 0 init (both halves track state for both columns) ----
    const float m00 = startT[0] + emb[0];
    float vA = __expf(startT[c0] + emb[c0] - m00);
    float vB = __expf(startT[c1] + emb[c1] - m00);
    float logZ = m00;
    int   nstep = 0;
    if (h == 0) {
        sV[0][c0] = __float2half_rn(vA);
        sV[0][c1] = __float2half_rn(vB);
    }
    float wA = __expf(emb[CRF_T + c0] - SHIFT);
    float wB = __expf(emb[CRF_T + c1] - SHIFT);
    __syncthreads();

    // ---- one forward step: read buffer P, write buffer Q (compile-time) ----
#define CRF_STEP(SV, P, Q)                                                     \
    {                                                                          \
        const int sn = ((SV) + 1 < CRF_S) ? (SV) + 1 : (CRF_S - 1);            \
        const float enA = emb[(size_t)sn * CRF_T + c0];                        \
        const float enB = emb[(size_t)sn * CRF_T + c1];                        \
        const int mk = sMask[(SV)];                                            \
        const uint4* r = (const uint4*)&sV[(P)][64 * h];                       \
        const uint4 x0 = r[0];                                                 \
        __half2 A0 = __half2half2(__ushort_as_half(0));                        \
        __half2 A1 = A0, A2 = A0, A3 = A0;                                     \
        __half2 B0 = A0, B1 = A0, B2 = A0, B3 = A0;                            \
        A0 = __hfma2(u32_as_h2(x0.x), EhA[0], A0);                             \
        A1 = __hfma2(u32_as_h2(x0.y), EhA[1], A1);                             \
        A2 = __hfma2(u32_as_h2(x0.z), EhA[2], A2);                             \
        A3 = __hfma2(u32_as_h2(x0.w), EhA[3], A3);                             \
        B0 = __hfma2(u32_as_h2(x0.x), EhB[0], B0);                             \
        B1 = __hfma2(u32_as_h2(x0.y), EhB[1], B1);                             \
        B2 = __hfma2(u32_as_h2(x0.z), EhB[2], B2);                             \
        B3 = __hfma2(u32_as_h2(x0.w), EhB[3], B3);                             \
        _Pragma("unroll")                                                      \
        for (int i = 1; i < 8; i++) {                                          \
            const uint4 x = r[i];                                              \
            A0 = __hfma2(u32_as_h2(x.x), EhA[4 * i + 0], A0);                  \
            A1 = __hfma2(u32_as_h2(x.y), EhA[4 * i + 1], A1);                  \
            A2 = __hfma2(u32_as_h2(x.z), EhA[4 * i + 2], A2);                  \
            A3 = __hfma2(u32_as_h2(x.w), EhA[4 * i + 3], A3);                  \
            B0 = __hfma2(u32_as_h2(x.x), EhB[4 * i + 0], B0);                  \
            B1 = __hfma2(u32_as_h2(x.y), EhB[4 * i + 1], B1);                  \
            B2 = __hfma2(u32_as_h2(x.z), EhB[4 * i + 2], B2);                  \
            B3 = __hfma2(u32_as_h2(x.w), EhB[4 * i + 3], B3);                  \
        }                                                                      \
        const __half2 Ac = __hadd2(__hadd2(A0, A1), __hadd2(A2, A3));          \
        const __half2 Bc = __hadd2(__hadd2(B0, B1), __hadd2(B2, B3));          \
        const float2 fa = __half22float2(Ac);                                  \
        const float2 fb = __half22float2(Bc);                                  \
        const float pA = fa.x + fa.y;                                          \
        const float pB = fb.x + fb.y;                                          \
        const float dotA = pA + __shfl_xor_sync(0xffffffffu, pA, 16);          \
        const float dotB = pB + __shfl_xor_sync(0xffffffffu, pB, 16);          \
        float vnA = mk ? dotA * wA : vA;                                       \
        float vnB = mk ? dotB * wB : vB;                                       \
        nstep += mk;                                                           \
        if (((SV) & 3) == 0) { /* rescale: anchor = sum of v[0..7] (h0) */     \
            const __half2 c2 = __hadd2(__hadd2(u32_as_h2(x0.x),                \
                                               u32_as_h2(x0.y)),               \
                                       __hadd2(u32_as_h2(x0.z),                \
                                               u32_as_h2(x0.w)));              \
            const float2 cf = __half22float2(c2);                              \
            const float ccl = cf.x + cf.y;                                     \
            const float cc = __shfl_sync(0xffffffffu, ccl, lane & 15);         \
            const float inv = __fdividef(1.0f, cc);                            \
            vnA *= inv;                                                        \
            vnB *= inv;                                                        \
            logZ += __logf(cc);                                                \
        }                                                                      \
        if (h == 0) {                                                          \
            sV[(Q)][c0] = __float2half_rn(vnA);                                \
            sV[(Q)][c1] = __float2half_rn(vnB);                                \
        }                                                                      \
        vA = vnA;                                                              \
        vB = vnB;                                                              \
        wA = __expf(enA - SHIFT);                                              \
        wB = __expf(enB - SHIFT);                                              \
        __syncthreads();                                                       \
    }

    CRF_STEP(1, 0, 1);
    for (int s = 2; s < CRF_S; s += 2) {
        CRF_STEP(s, 1, 0);
        CRF_STEP(s + 1, 0, 1);
    }
#undef CRF_STEP

    logZ += (SHIFT + LN4) * (float)nstep;

    // ---- final: fwd = log(sum_col v * exp(end)) + logZ ----
    // Lanes l and l^16 hold identical (vA, vB); offsets 8,4,2,1 reduce within
    // each 16-lane group, so lane 0 holds the sum over this warp's 32 cols.
    {
        float t0 = vA * __expf(endT[c0]) + vB * __expf(endT[c1]);
#pragma unroll
        for (int off = 8; off; off >>= 1)
            t0 += __shfl_xor_sync(0xffffffffu, t0, off);
        if (lane == 0) sRed[warp] = t0;
    }
    __syncthreads();
    const float fwd = __logf((sRed[0] + sRed[1]) + (sRed[2] + sRed[3])) + logZ;

    // ---- gold score (fp32, fixed-order tree reduce) ----
    {
        float part = 0.f;
        int cnt = 0;
        for (int s = j; s < CRF_S; s += CRF_T) {
            const int mk = sMask[s] ? 1 : 0;
            cnt += mk;
            if (s >= 1 && mk) {
                const int tp = (int)sTags[s - 1];
                const int tc = (int)sTags[s];
                part += trans[tp * CRF_T + tc] + emb[(size_t)s * CRF_T + tc];
            }
        }
        sPart[j] = part;
        sCnt[j]  = cnt;
        __syncthreads();
#pragma unroll
        for (int stride = CRF_T / 2; stride > 0; stride >>= 1) {
            if (j < stride) {
                sPart[j] += sPart[j + stride];
                sCnt[j]  += sCnt[j + stride];
            }
            __syncthreads();
        }
        if (j == 0) {
            const int tg0 = (int)sTags[0];
            float gold = sPart[0] + startT[tg0] + emb[tg0];
            const int seq_end = sCnt[0] - 1;
            gold += endT[(int)sTags[seq_end]];
            g_diff[b] = fwd - gold;
        }
    }

    // ---- grid-finish: last CTA does the deterministic mean ----
    __syncthreads();
    if (j == 0) {
        __threadfence();
        const int ticket = atomicAdd(&g_arrived, 1);
        sLast = (ticket == CRF_B - 1);
    }
    __syncthreads();
    if (sLast) {
        __threadfence();
        float acc = g_diff[j] + g_diff[j + 128] + g_diff[j + 256] + g_diff[j + 384];
        sPart[j] = acc;
        __syncthreads();
#pragma unroll
        for (int stride = CRF_T / 2; stride > 0; stride >>= 1) {
            if (j < stride) sPart[j] += sPart[j + stride];
            __syncthreads();
        }
        if (j == 0) {
            out[0] = sPart[0] * (1.0f / (float)CRF_B);
            g_arrived = 0;
        }
    }
}

extern "C" void kernel_launch(void* const* d_in, const int* in_sizes, int n_in,
                              void* d_out, int out_size)
{
    const float* emissions = (const float*)d_in[0];
    const void*  tags      = d_in[1];
    const void*  mask      = d_in[2];
    const float* startT    = (const float*)d_in[3];
    const float* endT      = (const float*)d_in[4];
    const float* trans     = (const float*)d_in[5];
    float*       out       = (float*)d_out;

    crf_fused_kernel<<<CRF_B, CRF_T>>>(emissions, tags, mask,
                                       startT, endT, trans, out);
}

// round 14
// speedup vs baseline: 1.9143x; 1.0476x over previous
#include <cuda_runtime.h>
#include <cuda_fp16.h>
#include <cstdint>

// Problem constants (CRF_6262062317593): B=512, S=512, T=128
#define CRF_B 512
#define CRF_S 512
#define CRF_T 128
#define SHIFT 5.0f               // per-step normalizer in w = exp(em - SHIFT)
#define LN4   1.3862944f         // E is scaled by 1/4; tracked via logZ
#define LOG2E 1.44269504f
#define NS2   (-SHIFT * LOG2E)   // folded exp2 constant

// Scratch (device globals: allocations are forbidden).
__device__ float g_diff[CRF_B];
__device__ int   g_arrived = 0;

__device__ __forceinline__ __half2 u32_as_h2(unsigned int u) {
    return *reinterpret_cast<__half2*>(&u);
}

// ---------------------------------------------------------------------------
// Fused kernel: one batch per CTA, 128 threads. Thread (warp, lane) owns
// i-half h = lane>>4 and ADJACENT tag columns 2q, 2q+1 with
// q = 16*warp + (lane&15)  (warp covers cols [32w, 32w+32)).
// Per step: 8 LDS.128 feed both column half-dots (32 HFMA2 each, fp16 accs,
// E scaled 1/4); the two partials pack into ONE half2 -> ONE shfl_xor(16) ->
// HADD2 -> both dots. Next-emission prefetch is one LDG.64; V writeback is
// one packed STS.32. One __syncthreads per step.
// ---------------------------------------------------------------------------
__global__ __launch_bounds__(CRF_T, 4)
void crf_fused_kernel(const float* __restrict__ em,       // (B,S,T) f32
                      const void*  __restrict__ tags,     // (B,S) i32 or i64
                      const void*  __restrict__ mask,     // (B,S) i32 or u8
                      const float* __restrict__ startT,   // (T)
                      const float* __restrict__ endT,     // (T)
                      const float* __restrict__ trans,    // (T,T)
                      float* __restrict__ out)            // scalar
{
    const int b    = blockIdx.x;
    const int j    = threadIdx.x;       // 0..127
    const int lane = j & 31;
    const int warp = j >> 5;            // 0..3
    const int h    = lane >> 4;         // i-half (0: i<64, 1: i>=64)
    const int q    = warp * 16 + (lane & 15);
    const int c0   = 2 * q;             // even column
    const int c1   = c0 + 1;            // odd column

    const float* __restrict__ emb = em + (size_t)b * CRF_S * CRF_T;

    __shared__ __align__(16) __half sV[2][CRF_T];
    __shared__ float         sRed[4];
    __shared__ float         sPart[CRF_T];
    __shared__ int           sCnt[CRF_T];
    __shared__ unsigned char sMask[CRF_S];
    __shared__ short         sTags[CRF_S];
    __shared__ int           sDet[4];
    __shared__ int           sLast;

    // ---- inline dtype detect (validated R2: mask int32 on this harness) ----
    if (j < 64) {
        const unsigned int* tw = (const unsigned int*)tags;
        const unsigned int* mw = (const unsigned int*)mask;
        const int zero = (tw[2 * j + 1] == 0u) ? 1 : 0;
        const int big  = (mw[j] > 1u) ? 1 : 0;
        const unsigned zm = __ballot_sync(0xffffffffu, zero);
        const unsigned bm = __ballot_sync(0xffffffffu, big);
        if (lane == 0) { sDet[warp] = __popc(zm); sDet[2 + warp] = __popc(bm); }
    }
    __syncthreads();
    const int tags_is64 = ((sDet[0] + sDet[1]) >= 48);
    const int mask_is32 = ((sDet[2] + sDet[3]) == 0);

    // ---- stage mask + tags with detected widths ----
    if (mask_is32) {
        const int* m0 = (const int*)mask + (size_t)b * CRF_S;
        for (int s = j; s < CRF_S; s += CRF_T) sMask[s] = (m0[s] != 0);
    } else {
        const unsigned char* m0 = (const unsigned char*)mask + (size_t)b * CRF_S;
        for (int s = j; s < CRF_S; s += CRF_T) sMask[s] = (m0[s] != 0);
    }
    if (tags_is64) {
        const long long* t0 = (const long long*)tags + (size_t)b * CRF_S;
        for (int s = j; s < CRF_S; s += CRF_T) sTags[s] = (short)t0[s];
    } else {
        const int* t0 = (const int*)tags + (size_t)b * CRF_S;
        for (int s = j; s < CRF_S; s += CRF_T) sTags[s] = (short)t0[s];
    }

    // ---- E half-columns (scaled by 1/4) for cols c0, c1 over i-half h ----
    // EhA[k] = (E[i0+2k][c0], E[i0+2k+1][c0])/4, k = 0..31; i0 = 64h.
    __half2 EhA[32], EhB[32];
    {
        const int i0 = 64 * h;
#pragma unroll
        for (int k = 0; k < 32; k++) {
            const float a0 = 0.25f * __expf(trans[(i0 + 2 * k)     * CRF_T + c0]);
            const float a1 = 0.25f * __expf(trans[(i0 + 2 * k + 1) * CRF_T + c0]);
            EhA[k] = __floats2half2_rn(a0, a1);
            const float b0 = 0.25f * __expf(trans[(i0 + 2 * k)     * CRF_T + c1]);
            const float b1 = 0.25f * __expf(trans[(i0 + 2 * k + 1) * CRF_T + c1]);
            EhB[k] = __floats2half2_rn(b0, b1);
        }
    }

    // ---- t = 0 init (both halves track state for both columns) ----
    const float m00 = startT[0] + emb[0];
    const float2 e0 = *(const float2*)&emb[c0];
    float vA = __expf(startT[c0] + e0.x - m00);
    float vB = __expf(startT[c1] + e0.y - m00);
    float logZ = m00;
    int   nstep = 0;
    if (h == 0)
        *(__half2*)&sV[0][c0] = __floats2half2_rn(vA, vB);
    const float2 e1 = *(const float2*)&emb[CRF_T + c0];
    float wA = exp2f(fmaf(e1.x, LOG2E, NS2));
    float wB = exp2f(fmaf(e1.y, LOG2E, NS2));
    __syncthreads();

    // ---- one forward step: read buffer P, write buffer Q (compile-time) ----
#define CRF_STEP(SV, P, Q)                                                     \
    {                                                                          \
        const int sn = ((SV) + 1 < CRF_S) ? (SV) + 1 : (CRF_S - 1);            \
        const float2 en2 = *(const float2*)&emb[(size_t)sn * CRF_T + c0];      \
        const int mk = sMask[(SV)];                                            \
        const uint4* r = (const uint4*)&sV[(P)][64 * h];                       \
        const uint4 x0 = r[0];                                                 \
        __half2 A0 = __half2half2(__ushort_as_half(0));                        \
        __half2 A1 = A0, A2 = A0, A3 = A0;                                     \
        __half2 B0 = A0, B1 = A0, B2 = A0, B3 = A0;                            \
        A0 = __hfma2(u32_as_h2(x0.x), EhA[0], A0);                             \
        A1 = __hfma2(u32_as_h2(x0.y), EhA[1], A1);                             \
        A2 = __hfma2(u32_as_h2(x0.z), EhA[2], A2);                             \
        A3 = __hfma2(u32_as_h2(x0.w), EhA[3], A3);                             \
        B0 = __hfma2(u32_as_h2(x0.x), EhB[0], B0);                             \
        B1 = __hfma2(u32_as_h2(x0.y), EhB[1], B1);                             \
        B2 = __hfma2(u32_as_h2(x0.z), EhB[2], B2);                             \
        B3 = __hfma2(u32_as_h2(x0.w), EhB[3], B3);                             \
        _Pragma("unroll")                                                      \
        for (int i = 1; i < 8; i++) {                                          \
            const uint4 x = r[i];                                              \
            A0 = __hfma2(u32_as_h2(x.x), EhA[4 * i + 0], A0);                  \
            A1 = __hfma2(u32_as_h2(x.y), EhA[4 * i + 1], A1);                  \
            A2 = __hfma2(u32_as_h2(x.z), EhA[4 * i + 2], A2);                  \
            A3 = __hfma2(u32_as_h2(x.w), EhA[4 * i + 3], A3);                  \
            B0 = __hfma2(u32_as_h2(x.x), EhB[4 * i + 0], B0);                  \
            B1 = __hfma2(u32_as_h2(x.y), EhB[4 * i + 1], B1);                  \
            B2 = __hfma2(u32_as_h2(x.z), EhB[4 * i + 2], B2);                  \
            B3 = __hfma2(u32_as_h2(x.w), EhB[4 * i + 3], B3);                  \
        }                                                                      \
        const __half2 Ac = __hadd2(__hadd2(A0, A1), __hadd2(A2, A3));          \
        const __half2 Bc = __hadd2(__hadd2(B0, B1), __hadd2(B2, B3));          \
        __half2 P2 = __halves2half2(                                           \
            __hadd(__low2half(Ac), __high2half(Ac)),                           \
            __hadd(__low2half(Bc), __high2half(Bc)));                          \
        const unsigned int pu = *reinterpret_cast<unsigned int*>(&P2);         \
        const unsigned int qu = __shfl_xor_sync(0xffffffffu, pu, 16);          \
        const __half2 D2 = __hadd2(P2, u32_as_h2(qu));                         \
        const float2 fd = __half22float2(D2);                                  \
        float vnA = mk ? fd.x * wA : vA;                                       \
        float vnB = mk ? fd.y * wB : vB;                                       \
        nstep += mk;                                                           \
        if (((SV) & 3) == 0) { /* rescale: anchor = sum of v[0..7] (h0) */     \
            const __half2 c2 = __hadd2(__hadd2(u32_as_h2(x0.x),                \
                                               u32_as_h2(x0.y)),               \
                                       __hadd2(u32_as_h2(x0.z),                \
                                               u32_as_h2(x0.w)));              \
            const float2 cf = __half22float2(c2);                              \
            const float ccl = cf.x + cf.y;                                     \
            const float cc = __shfl_sync(0xffffffffu, ccl, lane & 15);         \
            const float inv = __fdividef(1.0f, cc);                            \
            vnA *= inv;                                                        \
            vnB *= inv;                                                        \
            logZ += __logf(cc);                                                \
        }                                                                      \
        if (h == 0)                                                            \
            *(__half2*)&sV[(Q)][c0] = __floats2half2_rn(vnA, vnB);             \
        vA = vnA;                                                              \
        vB = vnB;                                                              \
        wA = exp2f(fmaf(en2.x, LOG2E, NS2));                                   \
        wB = exp2f(fmaf(en2.y, LOG2E, NS2));                                   \
        __syncthreads();                                                       \
    }

    CRF_STEP(1, 0, 1);
    for (int s = 2; s < CRF_S; s += 2) {
        CRF_STEP(s, 1, 0);
        CRF_STEP(s + 1, 0, 1);
    }
#undef CRF_STEP

    logZ += (SHIFT + LN4) * (float)nstep;

    // ---- final: fwd = log(sum_col v * exp(end)) + logZ ----
    // Lanes l and l^16 hold identical (vA, vB); offsets 8..1 reduce within
    // each 16-lane group; lane 0 holds the warp's 32-column sum.
    {
        float t0 = vA * __expf(endT[c0]) + vB * __expf(endT[c1]);
#pragma unroll
        for (int off = 8; off; off >>= 1)
            t0 += __shfl_xor_sync(0xffffffffu, t0, off);
        if (lane == 0) sRed[warp] = t0;
    }
    __syncthreads();
    const float fwd = __logf((sRed[0] + sRed[1]) + (sRed[2] + sRed[3])) + logZ;

    // ---- gold score (fp32, fixed-order tree reduce) ----
    {
        float part = 0.f;
        int cnt = 0;
        for (int s = j; s < CRF_S; s += CRF_T) {
            const int mk = sMask[s] ? 1 : 0;
            cnt += mk;
            if (s >= 1 && mk) {
                const int tp = (int)sTags[s - 1];
                const int tc = (int)sTags[s];
                part += trans[tp * CRF_T + tc] + emb[(size_t)s * CRF_T + tc];
            }
        }
        sPart[j] = part;
        sCnt[j]  = cnt;
        __syncthreads();
#pragma unroll
        for (int stride = CRF_T / 2; stride > 0; stride >>= 1) {
            if (j < stride) {
                sPart[j] += sPart[j + stride];
                sCnt[j]  += sCnt[j + stride];
            }
            __syncthreads();
        }
        if (j == 0) {
            const int tg0 = (int)sTags[0];
            float gold = sPart[0] + startT[tg0] + emb[tg0];
            const int seq_end = sCnt[0] - 1;
            gold += endT[(int)sTags[seq_end]];
            g_diff[b] = fwd - gold;
        }
    }

    // ---- grid-finish: last CTA does the deterministic mean ----
    __syncthreads();
    if (j == 0) {
        __threadfence();
        const int ticket = atomicAdd(&g_arrived, 1);
        sLast = (ticket == CRF_B - 1);
    }
    __syncthreads();
    if (sLast) {
        __threadfence();
        float acc = g_diff[j] + g_diff[j + 128] + g_diff[j + 256] + g_diff[j + 384];
        sPart[j] = acc;
        __syncthreads();
#pragma unroll
        for (int stride = CRF_T / 2; stride > 0; stride >>= 1) {
            if (j < stride) sPart[j] += sPart[j + stride];
            __syncthreads();
        }
        if (j == 0) {
            out[0] = sPart[0] * (1.0f / (float)CRF_B);
            g_arrived = 0;
        }
    }
}

extern "C" void kernel_launch(void* const* d_in, const int* in_sizes, int n_in,
                              void* d_out, int out_size)
{
    const float* emissions = (const float*)d_in[0];
    const void*  tags      = d_in[1];
    const void*  mask      = d_in[2];
    const float* startT    = (const float*)d_in[3];
    const float* endT      = (const float*)d_in[4];
    const float* trans     = (const float*)d_in[5];
    float*       out       = (float*)d_out;

    crf_fused_kernel<<<CRF_B, CRF_T>>>(emissions, tags, mask,
                                       startT, endT, trans, out);
}

// round 15
// speedup vs baseline: 1.9413x; 1.0141x over previous
#include <cuda_runtime.h>
#include <cuda_fp16.h>
#include <cstdint>

// Problem constants (CRF_6262062317593): B=512, S=512, T=128
#define CRF_B 512
#define CRF_S 512
#define CRF_T 128
#define SHIFT 4.0f               // per-step normalizer: mass multiplier ~0.97
#define LN4   1.3862944f         // E is scaled by 1/4; tracked via logZ
#define LOG2E 1.44269504f
#define NS2   (-SHIFT * LOG2E)   // folded exp2 constant

// Scratch (device globals: allocations are forbidden).
__device__ float g_diff[CRF_B];
__device__ int   g_arrived = 0;

__device__ __forceinline__ __half2 u32_as_h2(unsigned int u) {
    return *reinterpret_cast<__half2*>(&u);
}
__device__ __forceinline__ unsigned int h2_as_u32(__half2 h) {
    return *reinterpret_cast<unsigned int*>(&h);
}

// ---------------------------------------------------------------------------
// Fused kernel: one batch per CTA, 128 threads. Thread (warp, lane) owns
// i-half h = lane>>4 and ADJACENT tag columns 2q, 2q+1 (q = 16*warp+(lane&15)).
// Per step: 8 LDS.128 feed both column half-dots (fp16 accs, E scaled 1/4);
// partials pack -> ONE shfl_xor(16) -> HADD2 -> D2. State v and weight w stay
// PACKED half2 end-to-end: vn2 = HMUL2(D2,w2); mask-select = one SEL on u32;
// rescale (every 8 steps, SHIFT=4 keeps mass ~stable) = one HMUL2; STS direct.
// nstep precomputed once from the mask. One __syncthreads per step.
// ---------------------------------------------------------------------------
__global__ __launch_bounds__(CRF_T, 4)
void crf_fused_kernel(const float* __restrict__ em,       // (B,S,T) f32
                      const void*  __restrict__ tags,     // (B,S) i32 or i64
                      const void*  __restrict__ mask,     // (B,S) i32 or u8
                      const float* __restrict__ startT,   // (T)
                      const float* __restrict__ endT,     // (T)
                      const float* __restrict__ trans,    // (T,T)
                      float* __restrict__ out)            // scalar
{
    const int b    = blockIdx.x;
    const int j    = threadIdx.x;       // 0..127
    const int lane = j & 31;
    const int warp = j >> 5;            // 0..3
    const int h    = lane >> 4;         // i-half (0: i<64, 1: i>=64)
    const int q    = warp * 16 + (lane & 15);
    const int c0   = 2 * q;             // even column
    const int c1   = c0 + 1;            // odd column

    const float* __restrict__ emb = em + (size_t)b * CRF_S * CRF_T;

    __shared__ __align__(16) __half sV[2][CRF_T];
    __shared__ float         sRed[4];
    __shared__ float         sPart[CRF_T];
    __shared__ int           sCnt[CRF_T];
    __shared__ unsigned char sMask[CRF_S];
    __shared__ short         sTags[CRF_S];
    __shared__ int           sDet[4];
    __shared__ int           sLast;

    // ---- inline dtype detect (validated R2: mask int32 on this harness) ----
    if (j < 64) {
        const unsigned int* tw = (const unsigned int*)tags;
        const unsigned int* mw = (const unsigned int*)mask;
        const int zero = (tw[2 * j + 1] == 0u) ? 1 : 0;
        const int big  = (mw[j] > 1u) ? 1 : 0;
        const unsigned zm = __ballot_sync(0xffffffffu, zero);
        const unsigned bm = __ballot_sync(0xffffffffu, big);
        if (lane == 0) { sDet[warp] = __popc(zm); sDet[2 + warp] = __popc(bm); }
    }
    __syncthreads();
    const int tags_is64 = ((sDet[0] + sDet[1]) >= 48);
    const int mask_is32 = ((sDet[2] + sDet[3]) == 0);

    // ---- stage mask + tags; count masked steps while staging ----
    int myCnt = 0;
    if (mask_is32) {
        const int* m0 = (const int*)mask + (size_t)b * CRF_S;
        for (int s = j; s < CRF_S; s += CRF_T) {
            const unsigned char mv = (m0[s] != 0);
            sMask[s] = mv; myCnt += mv;
        }
    } else {
        const unsigned char* m0 = (const unsigned char*)mask + (size_t)b * CRF_S;
        for (int s = j; s < CRF_S; s += CRF_T) {
            const unsigned char mv = (m0[s] != 0);
            sMask[s] = mv; myCnt += mv;
        }
    }
    if (tags_is64) {
        const long long* t0 = (const long long*)tags + (size_t)b * CRF_S;
        for (int s = j; s < CRF_S; s += CRF_T) sTags[s] = (short)t0[s];
    } else {
        const int* t0 = (const int*)tags + (size_t)b * CRF_S;
        for (int s = j; s < CRF_S; s += CRF_T) sTags[s] = (short)t0[s];
    }
    sCnt[j] = myCnt;
    __syncthreads();
#pragma unroll
    for (int stride = CRF_T / 2; stride > 0; stride >>= 1) {
        if (j < stride) sCnt[j] += sCnt[j + stride];
        __syncthreads();
    }
    const int cntAll = sCnt[0];                         // total masked positions
    const int nstep  = cntAll - (sMask[0] ? 1 : 0);     // masked steps s>=1

    // ---- E half-columns (scaled by 1/4) for cols c0, c1 over i-half h ----
    __half2 EhA[32], EhB[32];
    {
        const int i0 = 64 * h;
#pragma unroll
        for (int k = 0; k < 32; k++) {
            const float a0 = 0.25f * __expf(trans[(i0 + 2 * k)     * CRF_T + c0]);
            const float a1 = 0.25f * __expf(trans[(i0 + 2 * k + 1) * CRF_T + c0]);
            EhA[k] = __floats2half2_rn(a0, a1);
            const float b0 = 0.25f * __expf(trans[(i0 + 2 * k)     * CRF_T + c1]);
            const float b1 = 0.25f * __expf(trans[(i0 + 2 * k + 1) * CRF_T + c1]);
            EhB[k] = __floats2half2_rn(b0, b1);
        }
    }

    // ---- t = 0 init: packed v state, packed w weights ----
    const float m00 = startT[0] + emb[0];
    const float2 e0 = *(const float2*)&emb[c0];
    unsigned int vPrev = h2_as_u32(__floats2half2_rn(
        __expf(startT[c0] + e0.x - m00),
        __expf(startT[c1] + e0.y - m00)));
    float logZ = m00;
    if (h == 0) *(unsigned int*)&sV[0][c0] = vPrev;
    const float2 e1 = *(const float2*)&emb[CRF_T + c0];
    __half2 w2 = __floats2half2_rn(exp2f(fmaf(e1.x, LOG2E, NS2)),
                                   exp2f(fmaf(e1.y, LOG2E, NS2)));
    __syncthreads();

    // ---- one forward step; PF=1 prefetches emissions for step SV+1 ----
#define CRF_STEP(SV, P, Q, PF)                                                 \
    {                                                                          \
        float2 en2;                                                            \
        if (PF) en2 = *(const float2*)&emb[(size_t)((SV) + 1) * CRF_T + c0];   \
        const int mk = sMask[(SV)];                                            \
        const uint4* r = (const uint4*)&sV[(P)][64 * h];                       \
        const uint4 x0 = r[0];                                                 \
        __half2 A0 = __half2half2(__ushort_as_half(0));                        \
        __half2 A1 = A0, A2 = A0, A3 = A0;                                     \
        __half2 B0 = A0, B1 = A0, B2 = A0, B3 = A0;                            \
        A0 = __hfma2(u32_as_h2(x0.x), EhA[0], A0);                             \
        A1 = __hfma2(u32_as_h2(x0.y), EhA[1], A1);                             \
        A2 = __hfma2(u32_as_h2(x0.z), EhA[2], A2);                             \
        A3 = __hfma2(u32_as_h2(x0.w), EhA[3], A3);                             \
        B0 = __hfma2(u32_as_h2(x0.x), EhB[0], B0);                             \
        B1 = __hfma2(u32_as_h2(x0.y), EhB[1], B1);                             \
        B2 = __hfma2(u32_as_h2(x0.z), EhB[2], B2);                             \
        B3 = __hfma2(u32_as_h2(x0.w), EhB[3], B3);                             \
        _Pragma("unroll")                                                      \
        for (int i = 1; i < 8; i++) {                                          \
            const uint4 x = r[i];                                              \
            A0 = __hfma2(u32_as_h2(x.x), EhA[4 * i + 0], A0);                  \
            A1 = __hfma2(u32_as_h2(x.y), EhA[4 * i + 1], A1);                  \
            A2 = __hfma2(u32_as_h2(x.z), EhA[4 * i + 2], A2);                  \
            A3 = __hfma2(u32_as_h2(x.w), EhA[4 * i + 3], A3);                  \
            B0 = __hfma2(u32_as_h2(x.x), EhB[4 * i + 0], B0);                  \
            B1 = __hfma2(u32_as_h2(x.y), EhB[4 * i + 1], B1);                  \
            B2 = __hfma2(u32_as_h2(x.z), EhB[4 * i + 2], B2);                  \
            B3 = __hfma2(u32_as_h2(x.w), EhB[4 * i + 3], B3);                  \
        }                                                                      \
        const __half2 Ac = __hadd2(__hadd2(A0, A1), __hadd2(A2, A3));          \
        const __half2 Bc = __hadd2(__hadd2(B0, B1), __hadd2(B2, B3));          \
        const __half2 P2 = __halves2half2(                                     \
            __hadd(__low2half(Ac), __high2half(Ac)),                           \
            __hadd(__low2half(Bc), __high2half(Bc)));                          \
        const unsigned int pu = h2_as_u32(P2);                                 \
        const unsigned int qu = __shfl_xor_sync(0xffffffffu, pu, 16);          \
        const __half2 D2 = __hadd2(P2, u32_as_h2(qu));                         \
        unsigned int vn = mk ? h2_as_u32(__hmul2(D2, w2)) : vPrev;             \
        if (((SV) & 7) == 0) { /* rescale: anchor = sum of v[0..7] (h0) */     \
            const __half2 c2 = __hadd2(__hadd2(u32_as_h2(x0.x),                \
                                               u32_as_h2(x0.y)),               \
                                       __hadd2(u32_as_h2(x0.z),                \
                                               u32_as_h2(x0.w)));              \
            const float2 cf = __half22float2(c2);                              \
            const float ccl = cf.x + cf.y;                                     \
            const float cc = __shfl_sync(0xffffffffu, ccl, lane & 15);         \
            const __half2 inv2 = __float2half2_rn(__fdividef(1.0f, cc));       \
            vn = h2_as_u32(__hmul2(u32_as_h2(vn), inv2));                      \
            logZ += __logf(cc);                                                \
        }                                                                      \
        if (h == 0) *(unsigned int*)&sV[(Q)][c0] = vn;                         \
        vPrev = vn;                                                            \
        if (PF) w2 = __floats2half2_rn(exp2f(fmaf(en2.x, LOG2E, NS2)),         \
                                       exp2f(fmaf(en2.y, LOG2E, NS2)));        \
        __syncthreads();                                                       \
    }

    CRF_STEP(1, 0, 1, 1);
    for (int s = 2; s < CRF_S - 2; s += 2) {
        CRF_STEP(s, 1, 0, 1);
        CRF_STEP(s + 1, 0, 1, 1);
    }
    CRF_STEP(CRF_S - 2, 1, 0, 1);
    CRF_STEP(CRF_S - 1, 0, 1, 0);
#undef CRF_STEP

    logZ += (SHIFT + LN4) * (float)nstep;

    // ---- final: fwd = log(sum_col v * exp(end)) + logZ ----
    // Lanes l and l^16 hold identical v; offsets 8..1 reduce each 16-group.
    {
        const float2 vf = __half22float2(u32_as_h2(vPrev));
        float t0 = vf.x * __expf(endT[c0]) + vf.y * __expf(endT[c1]);
#pragma unroll
        for (int off = 8; off; off >>= 1)
            t0 += __shfl_xor_sync(0xffffffffu, t0, off);
        if (lane == 0) sRed[warp] = t0;
    }
    __syncthreads();
    const float fwd = __logf((sRed[0] + sRed[1]) + (sRed[2] + sRed[3])) + logZ;

    // ---- gold score (fp32, fixed-order tree reduce; cnt precomputed) ----
    {
        float part = 0.f;
        for (int s = j; s < CRF_S; s += CRF_T) {
            if (s >= 1 && sMask[s]) {
                const int tp = (int)sTags[s - 1];
                const int tc = (int)sTags[s];
                part += trans[tp * CRF_T + tc] + emb[(size_t)s * CRF_T + tc];
            }
        }
        sPart[j] = part;
        __syncthreads();
#pragma unroll
        for (int stride = CRF_T / 2; stride > 0; stride >>= 1) {
            if (j < stride) sPart[j] += sPart[j + stride];
            __syncthreads();
        }
        if (j == 0) {
            const int tg0 = (int)sTags[0];
            float gold = sPart[0] + startT[tg0] + emb[tg0];
            const int seq_end = cntAll - 1;
            gold += endT[(int)sTags[seq_end]];
            g_diff[b] = fwd - gold;
        }
    }

    // ---- grid-finish: last CTA does the deterministic mean ----
    __syncthreads();
    if (j == 0) {
        __threadfence();
        const int ticket = atomicAdd(&g_arrived, 1);
        sLast = (ticket == CRF_B - 1);
    }
    __syncthreads();
    if (sLast) {
        __threadfence();
        float acc = g_diff[j] + g_diff[j + 128] + g_diff[j + 256] + g_diff[j + 384];
        sPart[j] = acc;
        __syncthreads();
#pragma unroll
        for (int stride = CRF_T / 2; stride > 0; stride >>= 1) {
            if (j < stride) sPart[j] += sPart[j + stride];
            __syncthreads();
        }
        if (j == 0) {
            out[0] = sPart[0] * (1.0f / (float)CRF_B);
            g_arrived = 0;
        }
    }
}

extern "C" void kernel_launch(void* const* d_in, const int* in_sizes, int n_in,
                              void* d_out, int out_size)
{
    const float* emissions = (const float*)d_in[0];
    const void*  tags      = d_in[1];
    const void*  mask      = d_in[2];
    const float* startT    = (const float*)d_in[3];
    const float* endT      = (const float*)d_in[4];
    const float* trans     = (const float*)d_in[5];
    float*       out       = (float*)d_out;

    crf_fused_kernel<<<CRF_B, CRF_T>>>(emissions, tags, mask,
                                       startT, endT, trans, out);
}

// round 16
// speedup vs baseline: 1.9772x; 1.0185x over previous
#include <cuda_runtime.h>
#include <cuda_fp16.h>
#include <cstdint>

// Problem constants (CRF_6262062317593): B=512, S=512, T=128
#define CRF_B 512
#define CRF_S 512
#define CRF_T 128
#define SHIFT 4.0f               // per-step normalizer: mass multiplier ~0.97
#define LN4   1.3862944f         // E is scaled by 1/4; tracked via logZ
#define LOG2E 1.44269504f
#define NS2   (-SHIFT * LOG2E)   // folded exp2 constant

// Scratch (device globals: allocations are forbidden).
__device__ float g_diff[CRF_B];
__device__ int   g_arrived = 0;

__device__ __forceinline__ __half2 u32_as_h2(unsigned int u) {
    return *reinterpret_cast<__half2*>(&u);
}
__device__ __forceinline__ unsigned int h2_as_u32(__half2 h) {
    return *reinterpret_cast<unsigned int*>(&h);
}

// ---------------------------------------------------------------------------
// Fused kernel: one batch per CTA, 128 threads. Thread (warp, lane) owns
// i-half h = lane>>4 and ADJACENT tag columns 2q, 2q+1 (q = 16*warp+(lane&15)).
// E is packed ACROSS COLUMNS: Eh2[k] = (E[i0+k][c0], E[i0+k][c1])/4, and v_i
// is broadcast into both halves via the HFMA2 half-lane selector
// (__low2half2/__high2half2 fold to .H0_H0/.H1_H1) — one HFMA2 per i-term
// covers both columns, and the 8 accumulators are (accA, accB)-packed so the
// combine is a pure HADD2 tree + one shfl_xor(16). State v and weight w stay
// packed half2 end-to-end; rescale every 8 steps (SHIFT=4). One barrier/step.
// ---------------------------------------------------------------------------
__global__ __launch_bounds__(CRF_T, 4)
void crf_fused_kernel(const float* __restrict__ em,       // (B,S,T) f32
                      const void*  __restrict__ tags,     // (B,S) i32 or i64
                      const void*  __restrict__ mask,     // (B,S) i32 or u8
                      const float* __restrict__ startT,   // (T)
                      const float* __restrict__ endT,     // (T)
                      const float* __restrict__ trans,    // (T,T)
                      float* __restrict__ out)            // scalar
{
    const int b    = blockIdx.x;
    const int j    = threadIdx.x;       // 0..127
    const int lane = j & 31;
    const int warp = j >> 5;            // 0..3
    const int h    = lane >> 4;         // i-half (0: i<64, 1: i>=64)
    const int q    = warp * 16 + (lane & 15);
    const int c0   = 2 * q;             // even column
    const int c1   = c0 + 1;            // odd column

    const float* __restrict__ emb = em + (size_t)b * CRF_S * CRF_T;

    __shared__ __align__(16) __half sV[2][CRF_T];
    __shared__ float         sRed[4];
    __shared__ float         sPart[CRF_T];
    __shared__ int           sCnt[CRF_T];
    __shared__ unsigned char sMask[CRF_S];
    __shared__ short         sTags[CRF_S];
    __shared__ int           sDet[4];
    __shared__ int           sLast;

    // ---- inline dtype detect (validated R2: mask int32 on this harness) ----
    if (j < 64) {
        const unsigned int* tw = (const unsigned int*)tags;
        const unsigned int* mw = (const unsigned int*)mask;
        const int zero = (tw[2 * j + 1] == 0u) ? 1 : 0;
        const int big  = (mw[j] > 1u) ? 1 : 0;
        const unsigned zm = __ballot_sync(0xffffffffu, zero);
        const unsigned bm = __ballot_sync(0xffffffffu, big);
        if (lane == 0) { sDet[warp] = __popc(zm); sDet[2 + warp] = __popc(bm); }
    }
    __syncthreads();
    const int tags_is64 = ((sDet[0] + sDet[1]) >= 48);
    const int mask_is32 = ((sDet[2] + sDet[3]) == 0);

    // ---- stage mask + tags; count masked steps while staging ----
    int myCnt = 0;
    if (mask_is32) {
        const int* m0 = (const int*)mask + (size_t)b * CRF_S;
        for (int s = j; s < CRF_S; s += CRF_T) {
            const unsigned char mv = (m0[s] != 0);
            sMask[s] = mv; myCnt += mv;
        }
    } else {
        const unsigned char* m0 = (const unsigned char*)mask + (size_t)b * CRF_S;
        for (int s = j; s < CRF_S; s += CRF_T) {
            const unsigned char mv = (m0[s] != 0);
            sMask[s] = mv; myCnt += mv;
        }
    }
    if (tags_is64) {
        const long long* t0 = (const long long*)tags + (size_t)b * CRF_S;
        for (int s = j; s < CRF_S; s += CRF_T) sTags[s] = (short)t0[s];
    } else {
        const int* t0 = (const int*)tags + (size_t)b * CRF_S;
        for (int s = j; s < CRF_S; s += CRF_T) sTags[s] = (short)t0[s];
    }
    sCnt[j] = myCnt;
    __syncthreads();
#pragma unroll
    for (int stride = CRF_T / 2; stride > 0; stride >>= 1) {
        if (j < stride) sCnt[j] += sCnt[j + stride];
        __syncthreads();
    }
    const int cntAll = sCnt[0];                         // total masked positions
    const int nstep  = cntAll - (sMask[0] ? 1 : 0);     // masked steps s>=1

    // ---- E packed across columns: Eh2[k] = (E[i0+k][c0], E[i0+k][c1])/4 ----
    __half2 Eh2[64];
    {
        const int i0 = 64 * h;
#pragma unroll
        for (int k = 0; k < 64; k++) {
            const float a = 0.25f * __expf(trans[(i0 + k) * CRF_T + c0]);
            const float c = 0.25f * __expf(trans[(i0 + k) * CRF_T + c1]);
            Eh2[k] = __floats2half2_rn(a, c);
        }
    }

    // ---- t = 0 init: packed v state, packed w weights ----
    const float m00 = startT[0] + emb[0];
    const float2 e0 = *(const float2*)&emb[c0];
    unsigned int vPrev = h2_as_u32(__floats2half2_rn(
        __expf(startT[c0] + e0.x - m00),
        __expf(startT[c1] + e0.y - m00)));
    float logZ = m00;
    if (h == 0) *(unsigned int*)&sV[0][c0] = vPrev;
    const float2 e1 = *(const float2*)&emb[CRF_T + c0];
    __half2 w2 = __floats2half2_rn(exp2f(fmaf(e1.x, LOG2E, NS2)),
                                   exp2f(fmaf(e1.y, LOG2E, NS2)));
    __syncthreads();

    // ---- one forward step; PF=1 prefetches emissions for step SV+1 ----
#define CRF_STEP(SV, P, Q, PF)                                                 \
    {                                                                          \
        float2 en2;                                                            \
        if (PF) en2 = *(const float2*)&emb[(size_t)((SV) + 1) * CRF_T + c0];   \
        const int mk = sMask[(SV)];                                            \
        const uint4* r = (const uint4*)&sV[(P)][64 * h];                       \
        const uint4 x0 = r[0];                                                 \
        __half2 A0 = __half2half2(__ushort_as_half(0));                        \
        __half2 A1 = A0, A2 = A0, A3 = A0;                                     \
        __half2 A4 = A0, A5 = A0, A6 = A0, A7 = A0;                            \
        A0 = __hfma2(__low2half2 (u32_as_h2(x0.x)), Eh2[0], A0);               \
        A1 = __hfma2(__high2half2(u32_as_h2(x0.x)), Eh2[1], A1);               \
        A2 = __hfma2(__low2half2 (u32_as_h2(x0.y)), Eh2[2], A2);               \
        A3 = __hfma2(__high2half2(u32_as_h2(x0.y)), Eh2[3], A3);               \
        A4 = __hfma2(__low2half2 (u32_as_h2(x0.z)), Eh2[4], A4);               \
        A5 = __hfma2(__high2half2(u32_as_h2(x0.z)), Eh2[5], A5);               \
        A6 = __hfma2(__low2half2 (u32_as_h2(x0.w)), Eh2[6], A6);               \
        A7 = __hfma2(__high2half2(u32_as_h2(x0.w)), Eh2[7], A7);               \
        _Pragma("unroll")                                                      \
        for (int i = 1; i < 8; i++) {                                          \
            const uint4 x = r[i];                                              \
            A0 = __hfma2(__low2half2 (u32_as_h2(x.x)), Eh2[8 * i + 0], A0);    \
            A1 = __hfma2(__high2half2(u32_as_h2(x.x)), Eh2[8 * i + 1], A1);    \
            A2 = __hfma2(__low2half2 (u32_as_h2(x.y)), Eh2[8 * i + 2], A2);    \
            A3 = __hfma2(__high2half2(u32_as_h2(x.y)), Eh2[8 * i + 3], A3);    \
            A4 = __hfma2(__low2half2 (u32_as_h2(x.z)), Eh2[8 * i + 4], A4);    \
            A5 = __hfma2(__high2half2(u32_as_h2(x.z)), Eh2[8 * i + 5], A5);    \
            A6 = __hfma2(__low2half2 (u32_as_h2(x.w)), Eh2[8 * i + 6], A6);    \
            A7 = __hfma2(__high2half2(u32_as_h2(x.w)), Eh2[8 * i + 7], A7);    \
        }                                                                      \
        const __half2 P2 = __hadd2(__hadd2(__hadd2(A0, A1), __hadd2(A2, A3)),  \
                                   __hadd2(__hadd2(A4, A5), __hadd2(A6, A7))); \
        const unsigned int pu = h2_as_u32(P2);                                 \
        const unsigned int qu = __shfl_xor_sync(0xffffffffu, pu, 16);          \
        const __half2 D2 = __hadd2(P2, u32_as_h2(qu));                         \
        unsigned int vn = mk ? h2_as_u32(__hmul2(D2, w2)) : vPrev;             \
        if (((SV) & 7) == 0) { /* rescale: anchor = sum of v[0..7] (h0) */     \
            const __half2 c2 = __hadd2(__hadd2(u32_as_h2(x0.x),                \
                                               u32_as_h2(x0.y)),               \
                                       __hadd2(u32_as_h2(x0.z),                \
                                               u32_as_h2(x0.w)));              \
            const float2 cf = __half22float2(c2);                              \
            const float ccl = cf.x + cf.y;                                     \
            const float cc = __shfl_sync(0xffffffffu, ccl, lane & 15);         \
            const __half2 inv2 = __float2half2_rn(__fdividef(1.0f, cc));       \
            vn = h2_as_u32(__hmul2(u32_as_h2(vn), inv2));                      \
            logZ += __logf(cc);                                                \
        }                                                                      \
        if (h == 0) *(unsigned int*)&sV[(Q)][c0] = vn;                         \
        vPrev = vn;                                                            \
        if (PF) w2 = __floats2half2_rn(exp2f(fmaf(en2.x, LOG2E, NS2)),         \
                                       exp2f(fmaf(en2.y, LOG2E, NS2)));        \
        __syncthreads();                                                       \
    }

    CRF_STEP(1, 0, 1, 1);
    for (int s = 2; s < CRF_S - 2; s += 2) {
        CRF_STEP(s, 1, 0, 1);
        CRF_STEP(s + 1, 0, 1, 1);
    }
    CRF_STEP(CRF_S - 2, 1, 0, 1);
    CRF_STEP(CRF_S - 1, 0, 1, 0);
#undef CRF_STEP

    logZ += (SHIFT + LN4) * (float)nstep;

    // ---- final: fwd = log(sum_col v * exp(end)) + logZ ----
    {
        const float2 vf = __half22float2(u32_as_h2(vPrev));
        float t0 = vf.x * __expf(endT[c0]) + vf.y * __expf(endT[c1]);
#pragma unroll
        for (int off = 8; off; off >>= 1)
            t0 += __shfl_xor_sync(0xffffffffu, t0, off);
        if (lane == 0) sRed[warp] = t0;
    }
    __syncthreads();
    const float fwd = __logf((sRed[0] + sRed[1]) + (sRed[2] + sRed[3])) + logZ;

    // ---- gold score (fp32, fixed-order tree reduce; cnt precomputed) ----
    {
        float part = 0.f;
        for (int s = j; s < CRF_S; s += CRF_T) {
            if (s >= 1 && sMask[s]) {
                const int tp = (int)sTags[s - 1];
                const int tc = (int)sTags[s];
                part += trans[tp * CRF_T + tc] + emb[(size_t)s * CRF_T + tc];
            }
        }
        sPart[j] = part;
        __syncthreads();
#pragma unroll
        for (int stride = CRF_T / 2; stride > 0; stride >>= 1) {
            if (j < stride) sPart[j] += sPart[j + stride];
            __syncthreads();
        }
        if (j == 0) {
            const int tg0 = (int)sTags[0];
            float gold = sPart[0] + startT[tg0] + emb[tg0];
            const int seq_end = cntAll - 1;
            gold += endT[(int)sTags[seq_end]];
            g_diff[b] = fwd - gold;
        }
    }

    // ---- grid-finish: last CTA does the deterministic mean ----
    __syncthreads();
    if (j == 0) {
        __threadfence();
        const int ticket = atomicAdd(&g_arrived, 1);
        sLast = (ticket == CRF_B - 1);
    }
    __syncthreads();
    if (sLast) {
        __threadfence();
        float acc = g_diff[j] + g_diff[j + 128] + g_diff[j + 256] + g_diff[j + 384];
        sPart[j] = acc;
        __syncthreads();
#pragma unroll
        for (int stride = CRF_T / 2; stride > 0; stride >>= 1) {
            if (j < stride) sPart[j] += sPart[j + stride];
            __syncthreads();
        }
        if (j == 0) {
            out[0] = sPart[0] * (1.0f / (float)CRF_B);
            g_arrived = 0;
        }
    }
}

extern "C" void kernel_launch(void* const* d_in, const int* in_sizes, int n_in,
                              void* d_out, int out_size)
{
    const float* emissions = (const float*)d_in[0];
    const void*  tags      = d_in[1];
    const void*  mask      = d_in[2];
    const float* startT    = (const float*)d_in[3];
    const float* endT      = (const float*)d_in[4];
    const float* trans     = (const float*)d_in[5];
    float*       out       = (float*)d_out;

    crf_fused_kernel<<<CRF_B, CRF_T>>>(emissions, tags, mask,
                                       startT, endT, trans, out);
}

// round 17
// speedup vs baseline: 2.0413x; 1.0324x over previous
#include <cuda_runtime.h>
#include <cuda_fp16.h>
#include <cstdint>

// Problem constants (CRF_6262062317593): B=512, S=512, T=128
#define CRF_B 512
#define CRF_S 512
#define CRF_T 128
#define SHIFT 4.0f               // per-step normalizer: mass multiplier ~0.97
#define LN4   1.3862944f         // E is scaled by 1/4; tracked via logZ
#define LOG2E 1.44269504f
#define NS2   (-SHIFT * LOG2E)   // folded exp2 constant

// Scratch (device globals: allocations are forbidden).
__device__ float g_diff[CRF_B];
__device__ int   g_arrived = 0;

__device__ __forceinline__ __half2 u32_as_h2(unsigned int u) {
    return *reinterpret_cast<__half2*>(&u);
}
__device__ __forceinline__ unsigned int h2_as_u32(__half2 h) {
    return *reinterpret_cast<unsigned int*>(&h);
}

// ---------------------------------------------------------------------------
// Fused kernel: one batch per CTA, 128 threads. Thread (warp, lane) owns
// i-half h = lane>>4 and ADJACENT tag columns 2q, 2q+1 (q = 16*warp+(lane&15)).
// E packed ACROSS COLUMNS (Eh2[k] = (E[i][c0], E[i][c1])/4); v_i broadcast via
// the HFMA2 half-lane selector, so one HFMA2 covers both columns and the
// combine is a pure HADD2 tree + one shfl_xor(16). State/weights stay packed
// half2. Rescale cadence (every 8 steps) is STRUCTURAL: the time loop is
// tiled in 8-step blocks with a dedicated rescale step — no runtime (s&7)
// test, no branch. One __syncthreads per step.
// ---------------------------------------------------------------------------
__global__ __launch_bounds__(CRF_T, 4)
void crf_fused_kernel(const float* __restrict__ em,       // (B,S,T) f32
                      const void*  __restrict__ tags,     // (B,S) i32 or i64
                      const void*  __restrict__ mask,     // (B,S) i32 or u8
                      const float* __restrict__ startT,   // (T)
                      const float* __restrict__ endT,     // (T)
                      const float* __restrict__ trans,    // (T,T)
                      float* __restrict__ out)            // scalar
{
    const int b    = blockIdx.x;
    const int j    = threadIdx.x;       // 0..127
    const int lane = j & 31;
    const int warp = j >> 5;            // 0..3
    const int h    = lane >> 4;         // i-half (0: i<64, 1: i>=64)
    const int q    = warp * 16 + (lane & 15);
    const int c0   = 2 * q;             // even column
    const int c1   = c0 + 1;            // odd column

    const float* __restrict__ emb = em + (size_t)b * CRF_S * CRF_T;

    __shared__ __align__(16) __half sV[2][CRF_T];
    __shared__ float         sRed[4];
    __shared__ float         sPart[CRF_T];
    __shared__ int           sCnt[CRF_T];
    __shared__ unsigned char sMask[CRF_S];
    __shared__ short         sTags[CRF_S];
    __shared__ int           sDet[4];
    __shared__ int           sLast;

    // ---- inline dtype detect (validated R2: mask int32 on this harness) ----
    if (j < 64) {
        const unsigned int* tw = (const unsigned int*)tags;
        const unsigned int* mw = (const unsigned int*)mask;
        const int zero = (tw[2 * j + 1] == 0u) ? 1 : 0;
        const int big  = (mw[j] > 1u) ? 1 : 0;
        const unsigned zm = __ballot_sync(0xffffffffu, zero);
        const unsigned bm = __ballot_sync(0xffffffffu, big);
        if (lane == 0) { sDet[warp] = __popc(zm); sDet[2 + warp] = __popc(bm); }
    }
    __syncthreads();
    const int tags_is64 = ((sDet[0] + sDet[1]) >= 48);
    const int mask_is32 = ((sDet[2] + sDet[3]) == 0);

    // ---- stage mask + tags; count masked steps while staging ----
    int myCnt = 0;
    if (mask_is32) {
        const int* m0 = (const int*)mask + (size_t)b * CRF_S;
        for (int s = j; s < CRF_S; s += CRF_T) {
            const unsigned char mv = (m0[s] != 0);
            sMask[s] = mv; myCnt += mv;
        }
    } else {
        const unsigned char* m0 = (const unsigned char*)mask + (size_t)b * CRF_S;
        for (int s = j; s < CRF_S; s += CRF_T) {
            const unsigned char mv = (m0[s] != 0);
            sMask[s] = mv; myCnt += mv;
        }
    }
    if (tags_is64) {
        const long long* t0 = (const long long*)tags + (size_t)b * CRF_S;
        for (int s = j; s < CRF_S; s += CRF_T) sTags[s] = (short)t0[s];
    } else {
        const int* t0 = (const int*)tags + (size_t)b * CRF_S;
        for (int s = j; s < CRF_S; s += CRF_T) sTags[s] = (short)t0[s];
    }
    sCnt[j] = myCnt;
    __syncthreads();
#pragma unroll
    for (int stride = CRF_T / 2; stride > 0; stride >>= 1) {
        if (j < stride) sCnt[j] += sCnt[j + stride];
        __syncthreads();
    }
    const int cntAll = sCnt[0];                         // total masked positions
    const int nstep  = cntAll - (sMask[0] ? 1 : 0);     // masked steps s>=1

    // ---- E packed across columns: Eh2[k] = (E[i0+k][c0], E[i0+k][c1])/4 ----
    __half2 Eh2[64];
    {
        const int i0 = 64 * h;
#pragma unroll
        for (int k = 0; k < 64; k++) {
            const float a = 0.25f * __expf(trans[(i0 + k) * CRF_T + c0]);
            const float c = 0.25f * __expf(trans[(i0 + k) * CRF_T + c1]);
            Eh2[k] = __floats2half2_rn(a, c);
        }
    }

    // ---- t = 0 init: packed v state, packed w weights ----
    const float m00 = startT[0] + emb[0];
    const float2 e0 = *(const float2*)&emb[c0];
    unsigned int vPrev = h2_as_u32(__floats2half2_rn(
        __expf(startT[c0] + e0.x - m00),
        __expf(startT[c1] + e0.y - m00)));
    float logZ = m00;
    if (h == 0) *(unsigned int*)&sV[0][c0] = vPrev;
    const float2 e1 = *(const float2*)&emb[CRF_T + c0];
    __half2 w2 = __floats2half2_rn(exp2f(fmaf(e1.x, LOG2E, NS2)),
                                   exp2f(fmaf(e1.y, LOG2E, NS2)));
    __syncthreads();

    // ---- step core (shared by both variants); RESC: 0 = never, 1 = always --
#define CRF_STEP_CORE(SV, P, Q, PF, RESC)                                      \
    {                                                                          \
        float2 en2;                                                            \
        if (PF) en2 = *(const float2*)&emb[(size_t)((SV) + 1) * CRF_T + c0];   \
        const int mk = sMask[(SV)];                                            \
        const uint4* r = (const uint4*)&sV[(P)][64 * h];                       \
        const uint4 x0 = r[0];                                                 \
        __half2 A0 = __half2half2(__ushort_as_half(0));                        \
        __half2 A1 = A0, A2 = A0, A3 = A0;                                     \
        __half2 A4 = A0, A5 = A0, A6 = A0, A7 = A0;                            \
        A0 = __hfma2(__low2half2 (u32_as_h2(x0.x)), Eh2[0], A0);               \
        A1 = __hfma2(__high2half2(u32_as_h2(x0.x)), Eh2[1], A1);               \
        A2 = __hfma2(__low2half2 (u32_as_h2(x0.y)), Eh2[2], A2);               \
        A3 = __hfma2(__high2half2(u32_as_h2(x0.y)), Eh2[3], A3);               \
        A4 = __hfma2(__low2half2 (u32_as_h2(x0.z)), Eh2[4], A4);               \
        A5 = __hfma2(__high2half2(u32_as_h2(x0.z)), Eh2[5], A5);               \
        A6 = __hfma2(__low2half2 (u32_as_h2(x0.w)), Eh2[6], A6);               \
        A7 = __hfma2(__high2half2(u32_as_h2(x0.w)), Eh2[7], A7);               \
        _Pragma("unroll")                                                      \
        for (int i = 1; i < 8; i++) {                                          \
            const uint4 x = r[i];                                              \
            A0 = __hfma2(__low2half2 (u32_as_h2(x.x)), Eh2[8 * i + 0], A0);    \
            A1 = __hfma2(__high2half2(u32_as_h2(x.x)), Eh2[8 * i + 1], A1);    \
            A2 = __hfma2(__low2half2 (u32_as_h2(x.y)), Eh2[8 * i + 2], A2);    \
            A3 = __hfma2(__high2half2(u32_as_h2(x.y)), Eh2[8 * i + 3], A3);    \
            A4 = __hfma2(__low2half2 (u32_as_h2(x.z)), Eh2[8 * i + 4], A4);    \
            A5 = __hfma2(__high2half2(u32_as_h2(x.z)), Eh2[8 * i + 5], A5);    \
            A6 = __hfma2(__low2half2 (u32_as_h2(x.w)), Eh2[8 * i + 6], A6);    \
            A7 = __hfma2(__high2half2(u32_as_h2(x.w)), Eh2[8 * i + 7], A7);    \
        }                                                                      \
        const __half2 P2 = __hadd2(__hadd2(__hadd2(A0, A1), __hadd2(A2, A3)),  \
                                   __hadd2(__hadd2(A4, A5), __hadd2(A6, A7))); \
        const unsigned int pu = h2_as_u32(P2);                                 \
        const unsigned int qu = __shfl_xor_sync(0xffffffffu, pu, 16);          \
        const __half2 D2 = __hadd2(P2, u32_as_h2(qu));                         \
        unsigned int vn = mk ? h2_as_u32(__hmul2(D2, w2)) : vPrev;             \
        if (RESC) { /* rescale: anchor = sum of v[0..7] (this i-half's x0) */  \
            const __half2 c2 = __hadd2(__hadd2(u32_as_h2(x0.x),                \
                                               u32_as_h2(x0.y)),               \
                                       __hadd2(u32_as_h2(x0.z),                \
                                               u32_as_h2(x0.w)));              \
            const float2 cf = __half22float2(c2);                              \
            const float ccl = cf.x + cf.y;                                     \
            const float cc = __shfl_sync(0xffffffffu, ccl, lane & 15);         \
            const __half2 inv2 = __float2half2_rn(__fdividef(1.0f, cc));       \
            vn = h2_as_u32(__hmul2(u32_as_h2(vn), inv2));                      \
            logZ += __logf(cc);                                                \
        }                                                                      \
        if (h == 0) *(unsigned int*)&sV[(Q)][c0] = vn;                         \
        vPrev = vn;                                                            \
        if (PF) w2 = __floats2half2_rn(exp2f(fmaf(en2.x, LOG2E, NS2)),         \
                                       exp2f(fmaf(en2.y, LOG2E, NS2)));        \
        __syncthreads();                                                       \
    }
#define STEP_NR(SV, P, Q, PF) CRF_STEP_CORE(SV, P, Q, PF, 0)
#define STEP_R(SV, P, Q, PF)  CRF_STEP_CORE(SV, P, Q, PF, 1)

    // Steps 1..7 (no rescale; parity: odd s -> (0,1), even s -> (1,0))
    STEP_NR(1, 0, 1, 1);
    STEP_NR(2, 1, 0, 1); STEP_NR(3, 0, 1, 1);
    STEP_NR(4, 1, 0, 1); STEP_NR(5, 0, 1, 1);
    STEP_NR(6, 1, 0, 1); STEP_NR(7, 0, 1, 1);

    // Blocks of 8: rescale at block start (s0 = 8, 16, ..., 496)
    for (int s0 = 8; s0 < 504; s0 += 8) {
        STEP_R (s0,     1, 0, 1);
        STEP_NR(s0 + 1, 0, 1, 1); STEP_NR(s0 + 2, 1, 0, 1);
        STEP_NR(s0 + 3, 0, 1, 1); STEP_NR(s0 + 4, 1, 0, 1);
        STEP_NR(s0 + 5, 0, 1, 1); STEP_NR(s0 + 6, 1, 0, 1);
        STEP_NR(s0 + 7, 0, 1, 1);
    }

    // Final block 504..511 (last step: no prefetch)
    STEP_R (504, 1, 0, 1);
    STEP_NR(505, 0, 1, 1); STEP_NR(506, 1, 0, 1);
    STEP_NR(507, 0, 1, 1); STEP_NR(508, 1, 0, 1);
    STEP_NR(509, 0, 1, 1); STEP_NR(510, 1, 0, 1);
    STEP_NR(511, 0, 1, 0);
#undef STEP_NR
#undef STEP_R
#undef CRF_STEP_CORE

    logZ += (SHIFT + LN4) * (float)nstep;

    // ---- final: fwd = log(sum_col v * exp(end)) + logZ ----
    {
        const float2 vf = __half22float2(u32_as_h2(vPrev));
        float t0 = vf.x * __expf(endT[c0]) + vf.y * __expf(endT[c1]);
#pragma unroll
        for (int off = 8; off; off >>= 1)
            t0 += __shfl_xor_sync(0xffffffffu, t0, off);
        if (lane == 0) sRed[warp] = t0;
    }
    __syncthreads();
    const float fwd = __logf((sRed[0] + sRed[1]) + (sRed[2] + sRed[3])) + logZ;

    // ---- gold score (fp32, fixed-order tree reduce; cnt precomputed) ----
    {
        float part = 0.f;
        for (int s = j; s < CRF_S; s += CRF_T) {
            if (s >= 1 && sMask[s]) {
                const int tp = (int)sTags[s - 1];
                const int tc = (int)sTags[s];
                part += trans[tp * CRF_T + tc] + emb[(size_t)s * CRF_T + tc];
            }
        }
        sPart[j] = part;
        __syncthreads();
#pragma unroll
        for (int stride = CRF_T / 2; stride > 0; stride >>= 1) {
            if (j < stride) sPart[j] += sPart[j + stride];
            __syncthreads();
        }
        if (j == 0) {
            const int tg0 = (int)sTags[0];
            float gold = sPart[0] + startT[tg0] + emb[tg0];
            const int seq_end = cntAll - 1;
            gold += endT[(int)sTags[seq_end]];
            g_diff[b] = fwd - gold;
        }
    }

    // ---- grid-finish: last CTA does the deterministic mean ----
    __syncthreads();
    if (j == 0) {
        __threadfence();
        const int ticket = atomicAdd(&g_arrived, 1);
        sLast = (ticket == CRF_B - 1);
    }
    __syncthreads();
    if (sLast) {
        __threadfence();
        float acc = g_diff[j] + g_diff[j + 128] + g_diff[j + 256] + g_diff[j + 384];
        sPart[j] = acc;
        __syncthreads();
#pragma unroll
        for (int stride = CRF_T / 2; stride > 0; stride >>= 1) {
            if (j < stride) sPart[j] += sPart[j + stride];
            __syncthreads();
        }
        if (j == 0) {
            out[0] = sPart[0] * (1.0f / (float)CRF_B);
            g_arrived = 0;
        }
    }
}

extern "C" void kernel_launch(void* const* d_in, const int* in_sizes, int n_in,
                              void* d_out, int out_size)
{
    const float* emissions = (const float*)d_in[0];
    const void*  tags      = d_in[1];
    const void*  mask      = d_in[2];
    const float* startT    = (const float*)d_in[3];
    const float* endT      = (const float*)d_in[4];
    const float* trans     = (const float*)d_in[5];
    float*       out       = (float*)d_out;

    crf_fused_kernel<<<CRF_B, CRF_T>>>(emissions, tags, mask,
                                       startT, endT, trans, out);
}